// round 13
// baseline (speedup 1.0000x reference)
#include <cuda_runtime.h>
#include <cuda_fp16.h>
#include <cstdint>

// Problem constants
#define BATCH 4
#define SEQ   2048
#define DMODEL 1024
#define NHEAD 16
#define HDIM  64
#define MROWS (BATCH*SEQ)         // 8192

#define NEG_INF __int_as_float(0xff800000)
#define LOG2E 1.44269504f

// ---------------- scratch (device globals; no allocation allowed) ----------
#define NELEM (8192*1024)
__device__ __half g_ah[NELEM];                            // input x, fp16 hi only
__device__ __half g_wh[4*1024*1024], g_wl[4*1024*1024];   // Wq,Wk,Wv,Wo hi/lo
__device__ __half g_qhh[NELEM];                           // Q heads (pre-scaled) hi
__device__ __half g_khh[NELEM], g_khl[NELEM];             // K heads hi/lo
__device__ __half g_vhh[NELEM], g_vhl[NELEM];             // V heads hi/lo
__device__ __half g_oh[NELEM];                            // attn out hi only
__device__ unsigned char g_mask[BATCH*SEQ];
__device__ int g_mode;

// ---------------- mask dtype detection + canonicalization ------------------
__global__ void detect_mask_kernel(const unsigned char* __restrict__ p) {
    __shared__ int s1, s3;
    if (threadIdx.x == 0) { s1 = 0; s3 = 0; }
    __syncthreads();
    int l1 = 0, l3 = 0;
    for (int i = threadIdx.x; i < BATCH*SEQ; i += blockDim.x) {
        unsigned char v = p[i];
        int m = i & 3;
        if (m == 1 && v) l1 = 1;
        if (m == 3 && v) l3 = 1;
    }
    if (l1) atomicOr(&s1, 1);
    if (l3) atomicOr(&s3, 1);
    __syncthreads();
    if (threadIdx.x == 0) g_mode = s1 ? 0 : (s3 ? 1 : 2);  // 0=u8, 1=f32, 2=i32
}

__global__ void convert_mask_kernel(const unsigned char* __restrict__ p) {
    int i = blockIdx.x * blockDim.x + threadIdx.x;
    if (i >= BATCH*SEQ) return;
    int mode = g_mode;
    unsigned char r;
    if (mode == 0)      r = (p[i] != 0);
    else if (mode == 1) r = (((const float*)p)[i] != 0.0f);
    else                r = (((const int*)p)[i] != 0);
    g_mask[i] = r;
}

// ---------------- fused prep: split 4 weights + convert input x --------------
#define WTOT (4*1024*1024)
__global__ void prep_kernel(const float* __restrict__ qx,
                            const float* __restrict__ w0, const float* __restrict__ w1,
                            const float* __restrict__ w2, const float* __restrict__ w3,
                            __half* __restrict__ ah,
                            __half* __restrict__ wh, __half* __restrict__ wl) {
    long i = ((long)blockIdx.x * blockDim.x + threadIdx.x) * 4;
    if (i < WTOT) {
        int z = (int)(i >> 20);
        const float* src = (z==0)?w0:(z==1)?w1:(z==2)?w2:w3;
        int off = (int)(i & 1048575);
        float4 v = *(const float4*)(src + off);
        float f[4] = {v.x, v.y, v.z, v.w};
        __half h[4], l[4];
        #pragma unroll
        for (int j = 0; j < 4; ++j) {
            h[j] = __float2half_rn(f[j]);
            l[j] = __float2half_rn(f[j] - __half2float(h[j]));
        }
        *(__half2*)(wh + i)     = __halves2half2(h[0], h[1]);
        *(__half2*)(wh + i + 2) = __halves2half2(h[2], h[3]);
        *(__half2*)(wl + i)     = __halves2half2(l[0], l[1]);
        *(__half2*)(wl + i + 2) = __halves2half2(l[2], l[3]);
    } else {
        long j = i - WTOT;
        float4 v = *(const float4*)(qx + j);
        *(__half2*)(ah + j)     = __floats2half2_rn(v.x, v.y);
        *(__half2*)(ah + j + 2) = __floats2half2_rn(v.z, v.w);
    }
}

// ---------------- mma / ldmatrix / cp.async primitives ----------------------
__device__ __forceinline__ void mma16816(float* c, const uint32_t* a, const uint32_t* b) {
    asm volatile(
        "mma.sync.aligned.m16n8k16.row.col.f32.f16.f16.f32 "
        "{%0,%1,%2,%3}, {%4,%5,%6,%7}, {%8,%9}, {%0,%1,%2,%3};"
        : "+f"(c[0]), "+f"(c[1]), "+f"(c[2]), "+f"(c[3])
        : "r"(a[0]), "r"(a[1]), "r"(a[2]), "r"(a[3]), "r"(b[0]), "r"(b[1]));
}
__device__ __forceinline__ void ldm_x4(uint32_t* r, uint32_t addr) {
    asm volatile("ldmatrix.sync.aligned.m8n8.x4.shared.b16 {%0,%1,%2,%3}, [%4];"
                 : "=r"(r[0]), "=r"(r[1]), "=r"(r[2]), "=r"(r[3]) : "r"(addr));
}
__device__ __forceinline__ void ldm_x4t(uint32_t* r, uint32_t addr) {
    asm volatile("ldmatrix.sync.aligned.m8n8.x4.trans.shared.b16 {%0,%1,%2,%3}, [%4];"
                 : "=r"(r[0]), "=r"(r[1]), "=r"(r[2]), "=r"(r[3]) : "r"(addr));
}
#define CP16(dst, src) \
    asm volatile("cp.async.cg.shared.global [%0], [%1], 16;" :: "r"(dst), "l"(src))
#define CP_COMMIT() asm volatile("cp.async.commit_group;" ::: "memory")
#define CP_WAIT(n)  asm volatile("cp.async.wait_group %0;" :: "n"(n) : "memory")

// ---------------- GEMM: C = A @ W^T + bias (fp16x2, 2-stage, occ 2) ---------
#define GSTG 49152
#define GNIT 16

template <bool SPLIT>
__global__ __launch_bounds__(256, 2) void gemm_cp_kernel(
    const __half* __restrict__ Ag,
    const __half* __restrict__ Whb, const __half* __restrict__ Wlb, int woff,
    const float* b0, const float* b1, const float* b2,
    __half* C0h, __half* C0l,
    __half* C1h, __half* C1l,
    __half* C2h, __half* C2l,
    float* Cf)
{
    int z = blockIdx.z;
    const __half* Wh = Whb + (size_t)(woff + z) * 1024 * 1024;
    const __half* Wl = Wlb + (size_t)(woff + z) * 1024 * 1024;
    const float* bias = (z == 0) ? b0 : (z == 1) ? b1 : b2;
    __half* Ch = (z == 0) ? C0h : (z == 1) ? C1h : C2h;
    __half* Cl = (z == 0) ? C0l : (z == 1) ? C1l : C2l;
    float outscale = (SPLIT && z == 0) ? (0.125f * LOG2E) : 1.0f;

    extern __shared__ __align__(128) unsigned char smraw[];
    uint32_t sb = (uint32_t)__cvta_generic_to_shared(smraw);

    int t = threadIdx.x, lane = t & 31, warp = t >> 5;
    int wm = warp >> 2, wn = warp & 3;
    int m0 = blockIdx.y * 128, n0 = blockIdx.x * 128;

    int row = t >> 1, half = t & 1;
    const __half* srcA  = Ag + (size_t)(m0 + row) * 1024 + half * 32;
    const __half* srcBh = Wh + (size_t)(n0 + row) * 1024 + half * 32;
    const __half* srcBl = Wl + (size_t)(n0 + row) * 1024 + half * 32;
    uint32_t rxor = (uint32_t)((row & 7) << 4);
    uint32_t dA = sb + row * 128;

    auto issue = [&](int ch) {
        uint32_t base = dA + (uint32_t)(ch & 1) * GSTG;
        const __half* sa = srcA  + ch * 64;
        const __half* sh = srcBh + ch * 64;
        const __half* sl = srcBl + ch * 64;
        #pragma unroll
        for (int j = 0; j < 4; ++j) {
            uint32_t c = (uint32_t)(half * 64 + j * 16) ^ rxor;
            CP16(base + c,         sa + j * 8);
            CP16(base + 16384 + c, sh + j * 8);
            CP16(base + 32768 + c, sl + j * 8);
        }
    };

    float c[4][4][4] = {};
    uint32_t x = (uint32_t)((lane & 7) << 4);
    uint32_t arowb = (uint32_t)((wm * 64 + (lane & 15)) * 128);
    uint32_t acol = (uint32_t)((lane >> 4) << 4);
    uint32_t browb = (uint32_t)((wn * 32 + (lane & 7) + ((lane >> 4) << 3)) * 128);
    uint32_t bcol = (uint32_t)(((lane >> 3) & 1) << 4);

    issue(0); CP_COMMIT();

    for (int it = 0; it < GNIT; ++it) {
        CP_WAIT(0);
        __syncthreads();
        if (it + 1 < GNIT) { issue(it + 1); CP_COMMIT(); }

        uint32_t Abase  = sb + (uint32_t)(it & 1) * GSTG;
        uint32_t Bhbase = Abase + 16384;
        uint32_t Blbase = Abase + 32768;
        #pragma unroll
        for (int kt = 0; kt < 4; ++kt) {
            uint32_t ac = ((uint32_t)(kt * 32) + acol) ^ x;
            uint32_t af[4][4];
            #pragma unroll
            for (int mi = 0; mi < 4; ++mi)
                ldm_x4(af[mi], Abase + arowb + mi * 16 * 128 + ac);
            uint32_t bc = ((uint32_t)(kt * 32) + bcol) ^ x;
            #pragma unroll
            for (int nip = 0; nip < 2; ++nip) {
                uint32_t baddr = browb + nip * 16 * 128 + bc;
                uint32_t bh4[4], bl4[4];
                ldm_x4(bh4, Bhbase + baddr);
                ldm_x4(bl4, Blbase + baddr);
                #pragma unroll
                for (int mi = 0; mi < 4; ++mi) {
                    mma16816(c[mi][2*nip],   af[mi], bh4);
                    mma16816(c[mi][2*nip],   af[mi], bl4);
                    mma16816(c[mi][2*nip+1], af[mi], bh4 + 2);
                    mma16816(c[mi][2*nip+1], af[mi], bl4 + 2);
                }
            }
        }
    }

    // epilogue
    int g = lane >> 2, cq = (lane & 3) * 2;
    #pragma unroll
    for (int mi = 0; mi < 4; ++mi) {
        int r0 = m0 + wm*64 + mi*16 + g;
        int r1 = r0 + 8;
        #pragma unroll
        for (int ni = 0; ni < 4; ++ni) {
            int col = n0 + wn*32 + ni*8 + cq;
            float b0v = __ldg(bias + col), b1v = __ldg(bias + col + 1);
            float v00 = c[mi][ni][0] + b0v, v01 = c[mi][ni][1] + b1v;
            float v10 = c[mi][ni][2] + b0v, v11 = c[mi][ni][3] + b1v;
            if (SPLIT) {
                int hh = col >> 6, hd = col & 63;
                int bi0 = r0 >> 11, s0 = r0 & 2047;
                int bi1 = r1 >> 11, s1 = r1 & 2047;
                size_t i0 = ((((size_t)bi0*NHEAD + hh)*SEQ) + s0)*HDIM + hd;
                size_t i1 = ((((size_t)bi1*NHEAD + hh)*SEQ) + s1)*HDIM + hd;
                __half2 h0 = __floats2half2_rn(v00 * outscale, v01 * outscale);
                __half2 h1 = __floats2half2_rn(v10 * outscale, v11 * outscale);
                *(__half2*)(Ch + i0) = h0;
                *(__half2*)(Ch + i1) = h1;
                if (Cl) {
                    __half2 l0 = __floats2half2_rn(v00 - __half2float(__low2half(h0)),
                                                   v01 - __half2float(__high2half(h0)));
                    __half2 l1 = __floats2half2_rn(v10 - __half2float(__low2half(h1)),
                                                   v11 - __half2float(__high2half(h1)));
                    *(__half2*)(Cl + i0) = l0;
                    *(__half2*)(Cl + i1) = l1;
                }
            } else {
                float2 v0 = {v00, v01}, v1 = {v10, v11};
                *(float2*)&Cf[(size_t)r0*DMODEL + col] = v0;
                *(float2*)&Cf[(size_t)r1*DMODEL + col] = v1;
            }
        }
    }
}

// ---------------- Flash attention (fp16x2, 128-q tile, 3-stage ring) --------
// grid (SEQ/128, B*H), 256 threads. Warp w owns query rows [w*16, w*16+16).
// 3-stage KV ring (32KB each): wait(1) at loop top -> each transfer gets ~2
// compute blocks to land; no transfer-latency exposure. Q stages via buf 2.
#define ASTG 32768
#define KM_OFF (3*ASTG)
#define ATTN_SMEM (KM_OFF + 3*64*4)

__global__ __launch_bounds__(256, 2) void attn_cp_kernel(
    const __half* __restrict__ qhh,
    const __half* __restrict__ khh, const __half* __restrict__ khl,
    const __half* __restrict__ vhh, const __half* __restrict__ vhl,
    __half* __restrict__ obh)
{
    extern __shared__ __align__(128) unsigned char smraw[];
    float* kmf = (float*)(smraw + KM_OFF);

    int t = threadIdx.x, lane = t & 31, w = t >> 5;
    int g = lane >> 2, cq = (lane & 3) * 2;
    int qt = blockIdx.x, bh = blockIdx.y;
    int b = bh >> 4, h = bh & 15;
    int q0 = qt * 128;
    size_t bhoff = (size_t)bh * SEQ * HDIM;
    const __half* qb = qhh + bhoff + (size_t)q0 * HDIM;
    const unsigned char* mb = g_mask + b * SEQ;

    uint32_t sbse = (uint32_t)__cvta_generic_to_shared(smraw);
    uint32_t x = (uint32_t)((lane & 7) << 4);

    // KV loading: 256 threads, each covers 32B of one row per region
    int rowq = t >> 2, part = t & 3;
    uint32_t rxq = (uint32_t)((rowq & 7) << 4);
    const __half* kvsrc[4] = {
        khh + bhoff + (size_t)rowq * HDIM + part * 16,
        khl + bhoff + (size_t)rowq * HDIM + part * 16,
        vhh + bhoff + (size_t)rowq * HDIM + part * 16,
        vhl + bhoff + (size_t)rowq * HDIM + part * 16 };

    auto issueKV = [&](int it2) {
        int st = it2 % 3;
        uint32_t base = sbse + st * ASTG + rowq * 128;
        size_t koff = (size_t)it2 * 64 * HDIM;
        #pragma unroll
        for (int rgn = 0; rgn < 4; ++rgn) {
            const __half* src = kvsrc[rgn] + koff;
            uint32_t db = base + rgn * 8192;
            #pragma unroll
            for (int j = 0; j < 2; ++j) {
                uint32_t c = (uint32_t)(part * 32 + j * 16) ^ rxq;
                CP16(db + c, src + j * 8);
            }
        }
        if (t < 64) kmf[st*64 + t] = mb[it2*64 + t] ? 0.0f : NEG_INF;
    };

    issueKV(0); CP_COMMIT();
    issueKV(1); CP_COMMIT();

    // stage Q (hi, 128 rows) through stage-2 buffer (overwritten at it=0,
    // after Q frags are in registers and the sync below has passed)
    {
        int rq = t >> 1, hq = t & 1;
        uint32_t qdst = sbse + 2*ASTG + rq * 128;
        const uint4* gq = (const uint4*)(qb + rq * HDIM + hq * 32);
        uint32_t rx = (uint32_t)((rq & 7) << 4);
        #pragma unroll
        for (int j = 0; j < 4; ++j) {
            uint32_t c = (uint32_t)(hq * 64 + j * 16) ^ rx;
            uint4 v = gq[j];
            asm volatile("st.shared.v4.b32 [%0], {%1,%2,%3,%4};" ::
                "r"(qdst + c), "r"(v.x), "r"(v.y), "r"(v.z), "r"(v.w));
        }
    }
    __syncthreads();
    uint32_t qf[4][4];
    {
        uint32_t qrow = (uint32_t)(w*16 + (lane & 15));
        uint32_t qc = (uint32_t)((lane >> 4) << 4);
        #pragma unroll
        for (int kt = 0; kt < 4; ++kt) {
            uint32_t c = ((uint32_t)(kt*32) + qc) ^ x;
            ldm_x4(qf[kt], sbse + 2*ASTG + qrow * 128 + c);
        }
    }

    float oc[8][4] = {};
    float m0r = NEG_INF, m1r = NEG_INF, l0r = 0.f, l1r = 0.f;
    uint32_t krow = (uint32_t)(lane & 7);
    uint32_t kq16 = (uint32_t)((lane >> 3) << 4);
    uint32_t vlr = (uint32_t)(lane & 15);
    uint32_t vsel = (uint32_t)((lane >> 4) << 4);

    const int NT = SEQ / 64;   // 32
    for (int it = 0; it < NT; ++it) {
        if (it + 1 < NT) { CP_WAIT(1); } else { CP_WAIT(0); }
        __syncthreads();     // stage it%3 visible; all warps done with it-1
        if (it + 2 < NT) { issueKV(it + 2); CP_COMMIT(); }

        uint32_t stage = sbse + (uint32_t)(it % 3) * ASTG;
        const uint32_t KhB = stage, KlB = stage + 8192;
        const uint32_t VhB = stage + 16384, VlB = stage + 24576;
        const float* km = kmf + (it % 3) * 64;

        // S = Qh Kh^T + Qh Kl^T  (16 rows x 64 keys per warp)
        float sc[8][4] = {};
        #pragma unroll
        for (int nt = 0; nt < 8; ++nt) {
            uint32_t rbase = ((uint32_t)(nt*8) + krow) * 128;
            #pragma unroll
            for (int ktp = 0; ktp < 2; ++ktp) {
                uint32_t c = ((uint32_t)(ktp*64) + kq16) ^ x;
                uint32_t kh4[4], kl4[4];
                ldm_x4(kh4, KhB + rbase + c);
                ldm_x4(kl4, KlB + rbase + c);
                mma16816(sc[nt], qf[2*ktp],   kh4);
                mma16816(sc[nt], qf[2*ktp],   kl4);
                mma16816(sc[nt], qf[2*ktp+1], kh4 + 2);
                mma16816(sc[nt], qf[2*ktp+1], kl4 + 2);
            }
        }

        // online softmax in exp2 domain (scores pre-scaled via Q)
        float r0m = NEG_INF, r1m = NEG_INF;
        #pragma unroll
        for (int nt = 0; nt < 8; ++nt) {
            float a0 = km[nt*8 + cq], a1 = km[nt*8 + cq + 1];
            sc[nt][0] += a0;
            sc[nt][1] += a1;
            sc[nt][2] += a0;
            sc[nt][3] += a1;
            r0m = fmaxf(r0m, fmaxf(sc[nt][0], sc[nt][1]));
            r1m = fmaxf(r1m, fmaxf(sc[nt][2], sc[nt][3]));
        }
        r0m = fmaxf(r0m, __shfl_xor_sync(0xffffffffu, r0m, 1));
        r0m = fmaxf(r0m, __shfl_xor_sync(0xffffffffu, r0m, 2));
        r1m = fmaxf(r1m, __shfl_xor_sync(0xffffffffu, r1m, 1));
        r1m = fmaxf(r1m, __shfl_xor_sync(0xffffffffu, r1m, 2));
        float mn0 = fmaxf(m0r, r0m), mn1 = fmaxf(m1r, r1m);
        float ms0 = (mn0 == NEG_INF) ? 0.0f : mn0;
        float ms1 = (mn1 == NEG_INF) ? 0.0f : mn1;
        float al0 = exp2f(m0r - ms0), al1 = exp2f(m1r - ms1);
        m0r = mn0; m1r = mn1;

        // exp2 + pack P (fp16 hi) directly into PV A-fragment registers
        uint32_t ph[8], ph2[8];
        float rs0 = 0.f, rs1 = 0.f;
        #pragma unroll
        for (int nt = 0; nt < 8; ++nt) {
            float p0 = exp2f(sc[nt][0] - ms0), p1 = exp2f(sc[nt][1] - ms0);
            float p2 = exp2f(sc[nt][2] - ms1), p3 = exp2f(sc[nt][3] - ms1);
            rs0 += p0 + p1; rs1 += p2 + p3;
            __half2 hv0 = __floats2half2_rn(p0, p1);
            __half2 hv1 = __floats2half2_rn(p2, p3);
            ph[nt]  = *(uint32_t*)&hv0;
            ph2[nt] = *(uint32_t*)&hv1;
        }
        rs0 += __shfl_xor_sync(0xffffffffu, rs0, 1);
        rs0 += __shfl_xor_sync(0xffffffffu, rs0, 2);
        rs1 += __shfl_xor_sync(0xffffffffu, rs1, 1);
        rs1 += __shfl_xor_sync(0xffffffffu, rs1, 2);
        l0r = l0r * al0 + rs0;
        l1r = l1r * al1 + rs1;
        #pragma unroll
        for (int nt = 0; nt < 8; ++nt) {
            oc[nt][0] *= al0; oc[nt][1] *= al0;
            oc[nt][2] *= al1; oc[nt][3] *= al1;
        }

        // O += Ph Vh + Ph Vl
        #pragma unroll
        for (int kt = 0; kt < 4; ++kt) {
            uint32_t pa[4] = {ph[2*kt], ph2[2*kt], ph[2*kt+1], ph2[2*kt+1]};
            uint32_t vr = ((uint32_t)(kt*16) + vlr) * 128;
            #pragma unroll
            for (int ntp = 0; ntp < 4; ++ntp) {
                uint32_t c = ((uint32_t)(ntp*32) + vsel) ^ x;
                uint32_t vh4[4], vl4[4];
                ldm_x4t(vh4, VhB + vr + c);
                ldm_x4t(vl4, VlB + vr + c);
                mma16816(oc[2*ntp],   pa, vh4);
                mma16816(oc[2*ntp],   pa, vl4);
                mma16816(oc[2*ntp+1], pa, vh4 + 2);
                mma16816(oc[2*ntp+1], pa, vl4 + 2);
            }
        }
    }

    // epilogue: normalize, zero masked query rows, write (b,s,d) as fp16 hi
    int r0 = w*16 + g, r1 = r0 + 8;
    float inv0 = (mb[q0 + r0] && l0r > 0.f) ? 1.0f / l0r : 0.0f;
    float inv1 = (mb[q0 + r1] && l1r > 0.f) ? 1.0f / l1r : 0.0f;
    size_t base0 = ((size_t)b*SEQ + q0 + r0)*DMODEL + h*HDIM;
    size_t base1 = ((size_t)b*SEQ + q0 + r1)*DMODEL + h*HDIM;
    #pragma unroll
    for (int nt = 0; nt < 8; ++nt) {
        __half2 h0 = __floats2half2_rn(oc[nt][0]*inv0, oc[nt][1]*inv0);
        __half2 h1 = __floats2half2_rn(oc[nt][2]*inv1, oc[nt][3]*inv1);
        *(__half2*)(obh + base0 + nt*8 + cq) = h0;
        *(__half2*)(obh + base1 + nt*8 + cq) = h1;
    }
}

// ---------------- launch ----------------------------------------------------
extern "C" void kernel_launch(void* const* d_in, const int* in_sizes, int n_in,
                              void* d_out, int out_size) {
    const float* q    = (const float*)d_in[0];
    const unsigned char* mask = (const unsigned char*)d_in[1];
    const float* Wq   = (const float*)d_in[2];
    const float* bq   = (const float*)d_in[3];
    const float* Wk   = (const float*)d_in[4];
    const float* bk   = (const float*)d_in[5];
    const float* Wv   = (const float*)d_in[6];
    const float* bv   = (const float*)d_in[7];
    const float* Wo   = (const float*)d_in[8];
    const float* bo   = (const float*)d_in[9];
    float* out = (float*)d_out;

    __half *ah, *wh, *wl, *qhh, *khh, *khl, *vhh, *vhl, *oh;
    cudaGetSymbolAddress((void**)&ah,  g_ah);
    cudaGetSymbolAddress((void**)&wh,  g_wh);
    cudaGetSymbolAddress((void**)&wl,  g_wl);
    cudaGetSymbolAddress((void**)&qhh, g_qhh);
    cudaGetSymbolAddress((void**)&khh, g_khh);
    cudaGetSymbolAddress((void**)&khl, g_khl);
    cudaGetSymbolAddress((void**)&vhh, g_vhh);
    cudaGetSymbolAddress((void**)&vhl, g_vhl);
    cudaGetSymbolAddress((void**)&oh,  g_oh);

    detect_mask_kernel<<<1, 256>>>(mask);
    convert_mask_kernel<<<(BATCH*SEQ + 255) / 256, 256>>>(mask);

    // fused prep: 12M fp32 elems (4M weight split + 8M input convert)
    prep_kernel<<<(WTOT + NELEM) / 1024, 256>>>(q, Wq, Wk, Wv, Wo, ah, wh, wl);

    const int gemm_smem = 2 * GSTG;   // 98304 B -> 2 CTAs/SM
    static bool attr_done = false;
    if (!attr_done) {
        cudaFuncSetAttribute(gemm_cp_kernel<true>,
                             cudaFuncAttributeMaxDynamicSharedMemorySize, gemm_smem);
        cudaFuncSetAttribute(gemm_cp_kernel<false>,
                             cudaFuncAttributeMaxDynamicSharedMemorySize, gemm_smem);
        cudaFuncSetAttribute(attn_cp_kernel,
                             cudaFuncAttributeMaxDynamicSharedMemorySize, ATTN_SMEM);
        attr_done = true;
    }

    // fused QKV projections (Q -> hi only, pre-scaled; K,V -> hi+lo)
    gemm_cp_kernel<true><<<dim3(8, 64, 3), 256, gemm_smem>>>(
        ah, wh, wl, 0, bq, bk, bv,
        qhh, nullptr, khh, khl, vhh, vhl, nullptr);

    attn_cp_kernel<<<dim3(SEQ / 128, BATCH * NHEAD), 256, ATTN_SMEM>>>(
        qhh, khh, khl, vhh, vhl, oh);

    // output projection -> fp32 out
    gemm_cp_kernel<false><<<dim3(8, 64, 1), 256, gemm_smem>>>(
        oh, wh, wl, 3, bo, bo, bo,
        nullptr, nullptr, nullptr, nullptr, nullptr, nullptr, out);
}

// round 14
// speedup vs baseline: 1.0305x; 1.0305x over previous
#include <cuda_runtime.h>
#include <cuda_fp16.h>
#include <cstdint>

// Problem constants
#define BATCH 4
#define SEQ   2048
#define DMODEL 1024
#define NHEAD 16
#define HDIM  64
#define MROWS (BATCH*SEQ)         // 8192

#define NEG_INF __int_as_float(0xff800000)
#define LOG2E 1.44269504f

// ---------------- scratch (device globals; no allocation allowed) ----------
#define NELEM (8192*1024)
__device__ __half g_ah[NELEM];                            // input x, fp16 hi only
__device__ __half g_wh[4*1024*1024], g_wl[4*1024*1024];   // Wq,Wk,Wv,Wo hi/lo
__device__ __half g_qhh[NELEM];                           // Q heads hi only
__device__ __half g_khh[NELEM], g_khl[NELEM];             // K heads hi/lo
__device__ __half g_vhh[NELEM], g_vhl[NELEM];             // V heads hi/lo
__device__ __half g_oh[NELEM];                            // attn out hi only
__device__ unsigned char g_mask[BATCH*SEQ];
__device__ int g_mode;

// ---------------- mask dtype detection + canonicalization ------------------
__global__ void detect_mask_kernel(const unsigned char* __restrict__ p) {
    __shared__ int s1, s3;
    if (threadIdx.x == 0) { s1 = 0; s3 = 0; }
    __syncthreads();
    int l1 = 0, l3 = 0;
    for (int i = threadIdx.x; i < BATCH*SEQ; i += blockDim.x) {
        unsigned char v = p[i];
        int m = i & 3;
        if (m == 1 && v) l1 = 1;
        if (m == 3 && v) l3 = 1;
    }
    if (l1) atomicOr(&s1, 1);
    if (l3) atomicOr(&s3, 1);
    __syncthreads();
    if (threadIdx.x == 0) g_mode = s1 ? 0 : (s3 ? 1 : 2);  // 0=u8, 1=f32, 2=i32
}

__global__ void convert_mask_kernel(const unsigned char* __restrict__ p) {
    int i = blockIdx.x * blockDim.x + threadIdx.x;
    if (i >= BATCH*SEQ) return;
    int mode = g_mode;
    unsigned char r;
    if (mode == 0)      r = (p[i] != 0);
    else if (mode == 1) r = (((const float*)p)[i] != 0.0f);
    else                r = (((const int*)p)[i] != 0);
    g_mask[i] = r;
}

// ---------------- fp32 -> fp16 conversion kernels ---------------------------
__global__ void tohalf_kernel(const float* __restrict__ src,
                              __half* __restrict__ hi, int n) {
    int i = (blockIdx.x * blockDim.x + threadIdx.x) * 4;
    if (i >= n) return;
    float4 v = *(const float4*)(src + i);
    *(__half2*)(hi + i)     = __floats2half2_rn(v.x, v.y);
    *(__half2*)(hi + i + 2) = __floats2half2_rn(v.z, v.w);
}

__global__ void split_w_kernel(const float* __restrict__ w0, const float* __restrict__ w1,
                               const float* __restrict__ w2, const float* __restrict__ w3,
                               __half* __restrict__ hi, __half* __restrict__ lo) {
    int z = blockIdx.z;
    const float* src = (z==0)?w0:(z==1)?w1:(z==2)?w2:w3;
    size_t off = (size_t)z * 1024 * 1024;
    int i = (blockIdx.x * blockDim.x + threadIdx.x) * 4;
    float4 v = *(const float4*)(src + i);
    float f[4] = {v.x, v.y, v.z, v.w};
    __half h[4], l[4];
    #pragma unroll
    for (int j = 0; j < 4; ++j) {
        h[j] = __float2half_rn(f[j]);
        l[j] = __float2half_rn(f[j] - __half2float(h[j]));
    }
    *(__half2*)(hi + off + i)     = __halves2half2(h[0], h[1]);
    *(__half2*)(hi + off + i + 2) = __halves2half2(h[2], h[3]);
    *(__half2*)(lo + off + i)     = __halves2half2(l[0], l[1]);
    *(__half2*)(lo + off + i + 2) = __halves2half2(l[2], l[3]);
}

// ---------------- mma / ldmatrix / cp.async primitives ----------------------
__device__ __forceinline__ void mma16816(float* c, const uint32_t* a, const uint32_t* b) {
    asm volatile(
        "mma.sync.aligned.m16n8k16.row.col.f32.f16.f16.f32 "
        "{%0,%1,%2,%3}, {%4,%5,%6,%7}, {%8,%9}, {%0,%1,%2,%3};"
        : "+f"(c[0]), "+f"(c[1]), "+f"(c[2]), "+f"(c[3])
        : "r"(a[0]), "r"(a[1]), "r"(a[2]), "r"(a[3]), "r"(b[0]), "r"(b[1]));
}
__device__ __forceinline__ void ldm_x4(uint32_t* r, uint32_t addr) {
    asm volatile("ldmatrix.sync.aligned.m8n8.x4.shared.b16 {%0,%1,%2,%3}, [%4];"
                 : "=r"(r[0]), "=r"(r[1]), "=r"(r[2]), "=r"(r[3]) : "r"(addr));
}
__device__ __forceinline__ void ldm_x4t(uint32_t* r, uint32_t addr) {
    asm volatile("ldmatrix.sync.aligned.m8n8.x4.trans.shared.b16 {%0,%1,%2,%3}, [%4];"
                 : "=r"(r[0]), "=r"(r[1]), "=r"(r[2]), "=r"(r[3]) : "r"(addr));
}
#define CP16(dst, src) \
    asm volatile("cp.async.cg.shared.global [%0], [%1], 16;" :: "r"(dst), "l"(src))
#define CP_COMMIT() asm volatile("cp.async.commit_group;" ::: "memory")
#define CP_WAIT(n)  asm volatile("cp.async.wait_group %0;" :: "n"(n) : "memory")

// ---------------- GEMM: C = A @ W^T + bias (fp16x2, 4-stage BK=32) ----------
// A: fp16 hi [M,1024]; W: fp16 hi/lo [N,1024]. BM=BN=128, BK=32.
// stage 24KB {A 8K, Bh 8K, Bl 8K}; 4 stages = 96KB -> 2 CTAs/SM.
// wait(2) at loop top -> each transfer has ~3 compute blocks to land.
// 64B rows; swizzle: byte16-chunk ^= ((row>>1)&3)<<4 (conflict-free ldmatrix).
#define GSTG 24576
#define GNIT 32

template <bool SPLIT>
__global__ __launch_bounds__(256, 2) void gemm_cp_kernel(
    const __half* __restrict__ Ag,
    const __half* __restrict__ Whb, const __half* __restrict__ Wlb, int woff,
    const float* b0, const float* b1, const float* b2,
    __half* C0h, __half* C0l,
    __half* C1h, __half* C1l,
    __half* C2h, __half* C2l,
    float* Cf)
{
    int z = blockIdx.z;
    const __half* Wh = Whb + (size_t)(woff + z) * 1024 * 1024;
    const __half* Wl = Wlb + (size_t)(woff + z) * 1024 * 1024;
    const float* bias = (z == 0) ? b0 : (z == 1) ? b1 : b2;
    __half* Ch = (z == 0) ? C0h : (z == 1) ? C1h : C2h;
    __half* Cl = (z == 0) ? C0l : (z == 1) ? C1l : C2l;

    extern __shared__ __align__(128) unsigned char smraw[];
    uint32_t sb = (uint32_t)__cvta_generic_to_shared(smraw);

    int t = threadIdx.x, lane = t & 31, warp = t >> 5;
    int wm = warp >> 2, wn = warp & 3;
    int m0 = blockIdx.y * 128, n0 = blockIdx.x * 128;

    // writer: thread t covers row=t>>1 (64B row), half=t&1 (32B)
    int row = t >> 1, half = t & 1;
    const __half* srcA  = Ag + (size_t)(m0 + row) * 1024 + half * 16;
    const __half* srcBh = Wh + (size_t)(n0 + row) * 1024 + half * 16;
    const __half* srcBl = Wl + (size_t)(n0 + row) * 1024 + half * 16;
    uint32_t wsw = (uint32_t)(((row >> 1) & 3) << 4);
    uint32_t dA = sb + row * 64;

    auto issue = [&](int ch) {
        uint32_t base = dA + (uint32_t)(ch & 3) * GSTG;
        const __half* sa = srcA  + ch * 32;
        const __half* sh = srcBh + ch * 32;
        const __half* sl = srcBl + ch * 32;
        #pragma unroll
        for (int j = 0; j < 2; ++j) {
            uint32_t c = (uint32_t)(half * 32 + j * 16) ^ wsw;
            CP16(base + c,         sa + j * 8);
            CP16(base + 8192 + c,  sh + j * 8);
            CP16(base + 16384 + c, sl + j * 8);
        }
    };

    float c[4][4][4] = {};
    // A frags: row0 = wm*64 + (lane&15); col chunk = (lane>>4)*16B
    uint32_t arow0 = (uint32_t)(wm * 64 + (lane & 15));
    uint32_t aswz = ((arow0 >> 1) & 3) << 4;
    uint32_t acol = (uint32_t)((lane >> 4) << 4);
    // B frags: row0 = wn*32 + (lane&7) + ((lane>>4)<<3); col chunk = ((lane>>3)&1)*16B
    uint32_t brow0 = (uint32_t)(wn * 32 + (lane & 7) + ((lane >> 4) << 3));
    uint32_t bswz = ((brow0 >> 1) & 3) << 4;
    uint32_t bcol = (uint32_t)(((lane >> 3) & 1) << 4);

    issue(0); CP_COMMIT();
    issue(1); CP_COMMIT();
    issue(2); CP_COMMIT();

    for (int it = 0; it < GNIT; ++it) {
        if (it + 2 < GNIT)      { CP_WAIT(2); }
        else if (it + 1 < GNIT) { CP_WAIT(1); }
        else                    { CP_WAIT(0); }
        __syncthreads();   // stage it%4 visible; all warps done with it-1
        if (it + 3 < GNIT) { issue(it + 3); CP_COMMIT(); }

        uint32_t Abase  = sb + (uint32_t)(it & 3) * GSTG;
        uint32_t Bhbase = Abase + 8192;
        uint32_t Blbase = Abase + 16384;
        #pragma unroll
        for (int kt = 0; kt < 2; ++kt) {
            uint32_t ac = ((uint32_t)(kt * 32) + acol) ^ aswz;
            uint32_t af[4][4];
            #pragma unroll
            for (int mi = 0; mi < 4; ++mi)
                ldm_x4(af[mi], Abase + (arow0 + mi * 16) * 64 + ac);
            uint32_t bc = ((uint32_t)(kt * 32) + bcol) ^ bswz;
            #pragma unroll
            for (int nip = 0; nip < 2; ++nip) {
                uint32_t baddr = (brow0 + nip * 16) * 64 + bc;
                uint32_t bh4[4], bl4[4];
                ldm_x4(bh4, Bhbase + baddr);
                ldm_x4(bl4, Blbase + baddr);
                #pragma unroll
                for (int mi = 0; mi < 4; ++mi) {
                    mma16816(c[mi][2*nip],   af[mi], bh4);
                    mma16816(c[mi][2*nip],   af[mi], bl4);
                    mma16816(c[mi][2*nip+1], af[mi], bh4 + 2);
                    mma16816(c[mi][2*nip+1], af[mi], bl4 + 2);
                }
            }
        }
    }

    // epilogue
    int g = lane >> 2, cq = (lane & 3) * 2;
    #pragma unroll
    for (int mi = 0; mi < 4; ++mi) {
        int r0 = m0 + wm*64 + mi*16 + g;
        int r1 = r0 + 8;
        #pragma unroll
        for (int ni = 0; ni < 4; ++ni) {
            int col = n0 + wn*32 + ni*8 + cq;
            float b0v = __ldg(bias + col), b1v = __ldg(bias + col + 1);
            float v00 = c[mi][ni][0] + b0v, v01 = c[mi][ni][1] + b1v;
            float v10 = c[mi][ni][2] + b0v, v11 = c[mi][ni][3] + b1v;
            if (SPLIT) {
                int hh = col >> 6, hd = col & 63;
                int bi0 = r0 >> 11, s0 = r0 & 2047;
                int bi1 = r1 >> 11, s1 = r1 & 2047;
                size_t i0 = ((((size_t)bi0*NHEAD + hh)*SEQ) + s0)*HDIM + hd;
                size_t i1 = ((((size_t)bi1*NHEAD + hh)*SEQ) + s1)*HDIM + hd;
                __half2 h0 = __floats2half2_rn(v00, v01);
                __half2 h1 = __floats2half2_rn(v10, v11);
                *(__half2*)(Ch + i0) = h0;
                *(__half2*)(Ch + i1) = h1;
                if (Cl) {
                    __half2 l0 = __floats2half2_rn(v00 - __half2float(__low2half(h0)),
                                                   v01 - __half2float(__high2half(h0)));
                    __half2 l1 = __floats2half2_rn(v10 - __half2float(__low2half(h1)),
                                                   v11 - __half2float(__high2half(h1)));
                    *(__half2*)(Cl + i0) = l0;
                    *(__half2*)(Cl + i1) = l1;
                }
            } else {
                float2 v0 = {v00, v01}, v1 = {v10, v11};
                *(float2*)&Cf[(size_t)r0*DMODEL + col] = v0;
                *(float2*)&Cf[(size_t)r1*DMODEL + col] = v1;
            }
        }
    }
}

// ---------------- Flash attention (R10: fp16x2, 128-q tile, 2-stage) --------
#define ASTG 32768
#define KM_OFF (2*ASTG)
#define ATTN_SMEM (KM_OFF + 2*64*4)

__global__ __launch_bounds__(256, 2) void attn_cp_kernel(
    const __half* __restrict__ qhh,
    const __half* __restrict__ khh, const __half* __restrict__ khl,
    const __half* __restrict__ vhh, const __half* __restrict__ vhl,
    __half* __restrict__ obh)
{
    extern __shared__ __align__(128) unsigned char smraw[];
    float* kmf = (float*)(smraw + KM_OFF);

    int t = threadIdx.x, lane = t & 31, w = t >> 5;
    int g = lane >> 2, cq = (lane & 3) * 2;
    int qt = blockIdx.x, bh = blockIdx.y;
    int b = bh >> 4, h = bh & 15;
    int q0 = qt * 128;
    size_t bhoff = (size_t)bh * SEQ * HDIM;
    const __half* qb = qhh + bhoff + (size_t)q0 * HDIM;
    const unsigned char* mb = g_mask + b * SEQ;

    uint32_t sbse = (uint32_t)__cvta_generic_to_shared(smraw);
    uint32_t x = (uint32_t)((lane & 7) << 4);

    int rowq = t >> 2, part = t & 3;
    uint32_t rxq = (uint32_t)((rowq & 7) << 4);
    const __half* kvsrc[4] = {
        khh + bhoff + (size_t)rowq * HDIM + part * 16,
        khl + bhoff + (size_t)rowq * HDIM + part * 16,
        vhh + bhoff + (size_t)rowq * HDIM + part * 16,
        vhl + bhoff + (size_t)rowq * HDIM + part * 16 };

    auto issueKV = [&](int it2) {
        int st = it2 & 1;
        uint32_t base = sbse + st * ASTG + rowq * 128;
        size_t koff = (size_t)it2 * 64 * HDIM;
        #pragma unroll
        for (int rgn = 0; rgn < 4; ++rgn) {
            const __half* src = kvsrc[rgn] + koff;
            uint32_t db = base + rgn * 8192;
            #pragma unroll
            for (int j = 0; j < 2; ++j) {
                uint32_t c = (uint32_t)(part * 32 + j * 16) ^ rxq;
                CP16(db + c, src + j * 8);
            }
        }
        if (t < 64) kmf[st*64 + t] = mb[it2*64 + t] ? 0.0f : NEG_INF;
    };

    issueKV(0); CP_COMMIT();

    // stage Q (hi, 128 rows) through stage-1 buffer
    {
        int rq = t >> 1, hq = t & 1;
        uint32_t qdst = sbse + ASTG + rq * 128;
        const uint4* gq = (const uint4*)(qb + rq * HDIM + hq * 32);
        uint32_t rx = (uint32_t)((rq & 7) << 4);
        #pragma unroll
        for (int j = 0; j < 4; ++j) {
            uint32_t c = (uint32_t)(hq * 64 + j * 16) ^ rx;
            uint4 v = gq[j];
            asm volatile("st.shared.v4.b32 [%0], {%1,%2,%3,%4};" ::
                "r"(qdst + c), "r"(v.x), "r"(v.y), "r"(v.z), "r"(v.w));
        }
    }
    __syncthreads();
    uint32_t qf[4][4];
    {
        uint32_t qrow = (uint32_t)(w*16 + (lane & 15));
        uint32_t qc = (uint32_t)((lane >> 4) << 4);
        #pragma unroll
        for (int kt = 0; kt < 4; ++kt) {
            uint32_t c = ((uint32_t)(kt*32) + qc) ^ x;
            ldm_x4(qf[kt], sbse + ASTG + qrow * 128 + c);
        }
    }
    __syncthreads();            // all warps have Q frags; stage 1 reusable

    float oc[8][4] = {};
    float m0r = NEG_INF, m1r = NEG_INF, l0r = 0.f, l1r = 0.f;
    uint32_t krow = (uint32_t)(lane & 7);
    uint32_t kq16 = (uint32_t)((lane >> 3) << 4);
    uint32_t vlr = (uint32_t)(lane & 15);
    uint32_t vsel = (uint32_t)((lane >> 4) << 4);
    const float SC2 = 0.125f * LOG2E;

    const int NT = SEQ / 64;   // 32
    for (int it = 0; it < NT; ++it) {
        CP_WAIT(0);
        __syncthreads();     // stage it visible; all warps done with it-1
        if (it + 1 < NT) { issueKV(it + 1); CP_COMMIT(); }

        uint32_t stage = sbse + (uint32_t)(it & 1) * ASTG;
        const uint32_t KhB = stage, KlB = stage + 8192;
        const uint32_t VhB = stage + 16384, VlB = stage + 24576;
        const float* km = kmf + (it & 1) * 64;

        // S = Qh Kh^T + Qh Kl^T
        float sc[8][4] = {};
        #pragma unroll
        for (int nt = 0; nt < 8; ++nt) {
            uint32_t rbase = ((uint32_t)(nt*8) + krow) * 128;
            #pragma unroll
            for (int ktp = 0; ktp < 2; ++ktp) {
                uint32_t c = ((uint32_t)(ktp*64) + kq16) ^ x;
                uint32_t kh4[4], kl4[4];
                ldm_x4(kh4, KhB + rbase + c);
                ldm_x4(kl4, KlB + rbase + c);
                mma16816(sc[nt], qf[2*ktp],   kh4);
                mma16816(sc[nt], qf[2*ktp],   kl4);
                mma16816(sc[nt], qf[2*ktp+1], kh4 + 2);
                mma16816(sc[nt], qf[2*ktp+1], kl4 + 2);
            }
        }

        // online softmax in exp2 domain
        float r0m = NEG_INF, r1m = NEG_INF;
        #pragma unroll
        for (int nt = 0; nt < 8; ++nt) {
            float a0 = km[nt*8 + cq], a1 = km[nt*8 + cq + 1];
            sc[nt][0] = sc[nt][0]*SC2 + a0;
            sc[nt][1] = sc[nt][1]*SC2 + a1;
            sc[nt][2] = sc[nt][2]*SC2 + a0;
            sc[nt][3] = sc[nt][3]*SC2 + a1;
            r0m = fmaxf(r0m, fmaxf(sc[nt][0], sc[nt][1]));
            r1m = fmaxf(r1m, fmaxf(sc[nt][2], sc[nt][3]));
        }
        r0m = fmaxf(r0m, __shfl_xor_sync(0xffffffffu, r0m, 1));
        r0m = fmaxf(r0m, __shfl_xor_sync(0xffffffffu, r0m, 2));
        r1m = fmaxf(r1m, __shfl_xor_sync(0xffffffffu, r1m, 1));
        r1m = fmaxf(r1m, __shfl_xor_sync(0xffffffffu, r1m, 2));
        float mn0 = fmaxf(m0r, r0m), mn1 = fmaxf(m1r, r1m);
        float ms0 = (mn0 == NEG_INF) ? 0.0f : mn0;
        float ms1 = (mn1 == NEG_INF) ? 0.0f : mn1;
        float al0 = exp2f(m0r - ms0), al1 = exp2f(m1r - ms1);
        m0r = mn0; m1r = mn1;

        uint32_t ph[8], ph2[8];
        float rs0 = 0.f, rs1 = 0.f;
        #pragma unroll
        for (int nt = 0; nt < 8; ++nt) {
            float p0 = exp2f(sc[nt][0] - ms0), p1 = exp2f(sc[nt][1] - ms0);
            float p2 = exp2f(sc[nt][2] - ms1), p3 = exp2f(sc[nt][3] - ms1);
            rs0 += p0 + p1; rs1 += p2 + p3;
            __half2 hv0 = __floats2half2_rn(p0, p1);
            __half2 hv1 = __floats2half2_rn(p2, p3);
            ph[nt]  = *(uint32_t*)&hv0;
            ph2[nt] = *(uint32_t*)&hv1;
        }
        rs0 += __shfl_xor_sync(0xffffffffu, rs0, 1);
        rs0 += __shfl_xor_sync(0xffffffffu, rs0, 2);
        rs1 += __shfl_xor_sync(0xffffffffu, rs1, 1);
        rs1 += __shfl_xor_sync(0xffffffffu, rs1, 2);
        l0r = l0r * al0 + rs0;
        l1r = l1r * al1 + rs1;
        #pragma unroll
        for (int nt = 0; nt < 8; ++nt) {
            oc[nt][0] *= al0; oc[nt][1] *= al0;
            oc[nt][2] *= al1; oc[nt][3] *= al1;
        }

        // O += Ph Vh + Ph Vl
        #pragma unroll
        for (int kt = 0; kt < 4; ++kt) {
            uint32_t pa[4] = {ph[2*kt], ph2[2*kt], ph[2*kt+1], ph2[2*kt+1]};
            uint32_t vr = ((uint32_t)(kt*16) + vlr) * 128;
            #pragma unroll
            for (int ntp = 0; ntp < 4; ++ntp) {
                uint32_t c = ((uint32_t)(ntp*32) + vsel) ^ x;
                uint32_t vh4[4], vl4[4];
                ldm_x4t(vh4, VhB + vr + c);
                ldm_x4t(vl4, VlB + vr + c);
                mma16816(oc[2*ntp],   pa, vh4);
                mma16816(oc[2*ntp],   pa, vl4);
                mma16816(oc[2*ntp+1], pa, vh4 + 2);
                mma16816(oc[2*ntp+1], pa, vl4 + 2);
            }
        }
    }

    // epilogue
    int r0 = w*16 + g, r1 = r0 + 8;
    float inv0 = (mb[q0 + r0] && l0r > 0.f) ? 1.0f / l0r : 0.0f;
    float inv1 = (mb[q0 + r1] && l1r > 0.f) ? 1.0f / l1r : 0.0f;
    size_t base0 = ((size_t)b*SEQ + q0 + r0)*DMODEL + h*HDIM;
    size_t base1 = ((size_t)b*SEQ + q0 + r1)*DMODEL + h*HDIM;
    #pragma unroll
    for (int nt = 0; nt < 8; ++nt) {
        __half2 h0 = __floats2half2_rn(oc[nt][0]*inv0, oc[nt][1]*inv0);
        __half2 h1 = __floats2half2_rn(oc[nt][2]*inv1, oc[nt][3]*inv1);
        *(__half2*)(obh + base0 + nt*8 + cq) = h0;
        *(__half2*)(obh + base1 + nt*8 + cq) = h1;
    }
}

// ---------------- launch ----------------------------------------------------
extern "C" void kernel_launch(void* const* d_in, const int* in_sizes, int n_in,
                              void* d_out, int out_size) {
    const float* q    = (const float*)d_in[0];
    const unsigned char* mask = (const unsigned char*)d_in[1];
    const float* Wq   = (const float*)d_in[2];
    const float* bq   = (const float*)d_in[3];
    const float* Wk   = (const float*)d_in[4];
    const float* bk   = (const float*)d_in[5];
    const float* Wv   = (const float*)d_in[6];
    const float* bv   = (const float*)d_in[7];
    const float* Wo   = (const float*)d_in[8];
    const float* bo   = (const float*)d_in[9];
    float* out = (float*)d_out;

    __half *ah, *wh, *wl, *qhh, *khh, *khl, *vhh, *vhl, *oh;
    cudaGetSymbolAddress((void**)&ah,  g_ah);
    cudaGetSymbolAddress((void**)&wh,  g_wh);
    cudaGetSymbolAddress((void**)&wl,  g_wl);
    cudaGetSymbolAddress((void**)&qhh, g_qhh);
    cudaGetSymbolAddress((void**)&khh, g_khh);
    cudaGetSymbolAddress((void**)&khl, g_khl);
    cudaGetSymbolAddress((void**)&vhh, g_vhh);
    cudaGetSymbolAddress((void**)&vhl, g_vhl);
    cudaGetSymbolAddress((void**)&oh,  g_oh);

    detect_mask_kernel<<<1, 256>>>(mask);
    convert_mask_kernel<<<(BATCH*SEQ + 255) / 256, 256>>>(mask);

    tohalf_kernel<<<NELEM / 1024, 256>>>(q, ah, NELEM);
    split_w_kernel<<<dim3(1024, 1, 4), 256>>>(Wq, Wk, Wv, Wo, wh, wl);

    const int gemm_smem = 4 * GSTG;   // 98304 B -> 2 CTAs/SM
    static bool attr_done = false;
    if (!attr_done) {
        cudaFuncSetAttribute(gemm_cp_kernel<true>,
                             cudaFuncAttributeMaxDynamicSharedMemorySize, gemm_smem);
        cudaFuncSetAttribute(gemm_cp_kernel<false>,
                             cudaFuncAttributeMaxDynamicSharedMemorySize, gemm_smem);
        cudaFuncSetAttribute(attn_cp_kernel,
                             cudaFuncAttributeMaxDynamicSharedMemorySize, ATTN_SMEM);
        attr_done = true;
    }

    // fused QKV projections (Q -> hi only; K,V -> hi+lo)
    gemm_cp_kernel<true><<<dim3(8, 64, 3), 256, gemm_smem>>>(
        ah, wh, wl, 0, bq, bk, bv,
        qhh, nullptr, khh, khl, vhh, vhl, nullptr);

    attn_cp_kernel<<<dim3(SEQ / 128, BATCH * NHEAD), 256, ATTN_SMEM>>>(
        qhh, khh, khl, vhh, vhl, oh);

    // output projection -> fp32 out
    gemm_cp_kernel<false><<<dim3(8, 64, 1), 256, gemm_smem>>>(
        oh, wh, wl, 3, bo, bo, bo,
        nullptr, nullptr, nullptr, nullptr, nullptr, nullptr, out);
}

// round 15
// speedup vs baseline: 1.1212x; 1.0880x over previous
#include <cuda_runtime.h>
#include <cuda_fp16.h>
#include <cstdint>

// Problem constants
#define BATCH 4
#define SEQ   2048
#define DMODEL 1024
#define NHEAD 16
#define HDIM  64
#define MROWS (BATCH*SEQ)         // 8192

#define NEG_INF __int_as_float(0xff800000)
#define LOG2E 1.44269504f

// ---------------- scratch (device globals; no allocation allowed) ----------
#define NELEM (8192*1024)
__device__ __half g_ah[NELEM];                            // input x, fp16 hi only
__device__ __half g_wh[4*1024*1024], g_wl[4*1024*1024];   // Wq,Wk,Wv,Wo hi/lo
__device__ __half g_qhh[NELEM];                           // Q heads hi only
__device__ __half g_khh[NELEM], g_khl[NELEM];             // K heads hi/lo
__device__ __half g_vhh[NELEM];                           // V heads hi only
__device__ __half g_oh[NELEM];                            // attn out hi only
__device__ unsigned char g_mask[BATCH*SEQ];
__device__ int g_mode;

// ---------------- mask dtype detection + canonicalization ------------------
__global__ void detect_mask_kernel(const unsigned char* __restrict__ p) {
    __shared__ int s1, s3;
    if (threadIdx.x == 0) { s1 = 0; s3 = 0; }
    __syncthreads();
    int l1 = 0, l3 = 0;
    for (int i = threadIdx.x; i < BATCH*SEQ; i += blockDim.x) {
        unsigned char v = p[i];
        int m = i & 3;
        if (m == 1 && v) l1 = 1;
        if (m == 3 && v) l3 = 1;
    }
    if (l1) atomicOr(&s1, 1);
    if (l3) atomicOr(&s3, 1);
    __syncthreads();
    if (threadIdx.x == 0) g_mode = s1 ? 0 : (s3 ? 1 : 2);  // 0=u8, 1=f32, 2=i32
}

__global__ void convert_mask_kernel(const unsigned char* __restrict__ p) {
    int i = blockIdx.x * blockDim.x + threadIdx.x;
    if (i >= BATCH*SEQ) return;
    int mode = g_mode;
    unsigned char r;
    if (mode == 0)      r = (p[i] != 0);
    else if (mode == 1) r = (((const float*)p)[i] != 0.0f);
    else                r = (((const int*)p)[i] != 0);
    g_mask[i] = r;
}

// ---------------- fp32 -> fp16 conversion kernels ---------------------------
__global__ void tohalf_kernel(const float* __restrict__ src,
                              __half* __restrict__ hi, int n) {
    int i = (blockIdx.x * blockDim.x + threadIdx.x) * 4;
    if (i >= n) return;
    float4 v = *(const float4*)(src + i);
    *(__half2*)(hi + i)     = __floats2half2_rn(v.x, v.y);
    *(__half2*)(hi + i + 2) = __floats2half2_rn(v.z, v.w);
}

__global__ void split_w_kernel(const float* __restrict__ w0, const float* __restrict__ w1,
                               const float* __restrict__ w2, const float* __restrict__ w3,
                               __half* __restrict__ hi, __half* __restrict__ lo) {
    int z = blockIdx.z;
    const float* src = (z==0)?w0:(z==1)?w1:(z==2)?w2:w3;
    size_t off = (size_t)z * 1024 * 1024;
    int i = (blockIdx.x * blockDim.x + threadIdx.x) * 4;
    float4 v = *(const float4*)(src + i);
    float f[4] = {v.x, v.y, v.z, v.w};
    __half h[4], l[4];
    #pragma unroll
    for (int j = 0; j < 4; ++j) {
        h[j] = __float2half_rn(f[j]);
        l[j] = __float2half_rn(f[j] - __half2float(h[j]));
    }
    *(__half2*)(hi + off + i)     = __halves2half2(h[0], h[1]);
    *(__half2*)(hi + off + i + 2) = __halves2half2(h[2], h[3]);
    *(__half2*)(lo + off + i)     = __halves2half2(l[0], l[1]);
    *(__half2*)(lo + off + i + 2) = __halves2half2(l[2], l[3]);
}

// ---------------- mma / ldmatrix / cp.async primitives ----------------------
__device__ __forceinline__ void mma16816(float* c, const uint32_t* a, const uint32_t* b) {
    asm volatile(
        "mma.sync.aligned.m16n8k16.row.col.f32.f16.f16.f32 "
        "{%0,%1,%2,%3}, {%4,%5,%6,%7}, {%8,%9}, {%0,%1,%2,%3};"
        : "+f"(c[0]), "+f"(c[1]), "+f"(c[2]), "+f"(c[3])
        : "r"(a[0]), "r"(a[1]), "r"(a[2]), "r"(a[3]), "r"(b[0]), "r"(b[1]));
}
__device__ __forceinline__ void ldm_x4(uint32_t* r, uint32_t addr) {
    asm volatile("ldmatrix.sync.aligned.m8n8.x4.shared.b16 {%0,%1,%2,%3}, [%4];"
                 : "=r"(r[0]), "=r"(r[1]), "=r"(r[2]), "=r"(r[3]) : "r"(addr));
}
__device__ __forceinline__ void ldm_x4t(uint32_t* r, uint32_t addr) {
    asm volatile("ldmatrix.sync.aligned.m8n8.x4.trans.shared.b16 {%0,%1,%2,%3}, [%4];"
                 : "=r"(r[0]), "=r"(r[1]), "=r"(r[2]), "=r"(r[3]) : "r"(addr));
}
#define CP16(dst, src) \
    asm volatile("cp.async.cg.shared.global [%0], [%1], 16;" :: "r"(dst), "l"(src))
#define CP_COMMIT() asm volatile("cp.async.commit_group;" ::: "memory")
#define CP_WAIT(n)  asm volatile("cp.async.wait_group %0;" :: "n"(n) : "memory")

// ---------------- GEMM: C = A @ W^T + bias (fp16x2, 2-stage, occ 2) ---------
// R10-proven config. LOSPLIT: whether to also write the fp16 lo residual.
#define GSTG 49152
#define GNIT 16

template <bool SPLIT>
__global__ __launch_bounds__(256, 2) void gemm_cp_kernel(
    const __half* __restrict__ Ag,
    const __half* __restrict__ Whb, const __half* __restrict__ Wlb, int woff,
    const float* b0, const float* b1, const float* b2,
    __half* C0h, __half* C0l,
    __half* C1h, __half* C1l,
    __half* C2h, __half* C2l,
    float* Cf)
{
    int z = blockIdx.z;
    const __half* Wh = Whb + (size_t)(woff + z) * 1024 * 1024;
    const __half* Wl = Wlb + (size_t)(woff + z) * 1024 * 1024;
    const float* bias = (z == 0) ? b0 : (z == 1) ? b1 : b2;
    __half* Ch = (z == 0) ? C0h : (z == 1) ? C1h : C2h;
    __half* Cl = (z == 0) ? C0l : (z == 1) ? C1l : C2l;

    extern __shared__ __align__(128) unsigned char smraw[];
    uint32_t sb = (uint32_t)__cvta_generic_to_shared(smraw);

    int t = threadIdx.x, lane = t & 31, warp = t >> 5;
    int wm = warp >> 2, wn = warp & 3;
    int m0 = blockIdx.y * 128, n0 = blockIdx.x * 128;

    int row = t >> 1, half = t & 1;
    const __half* srcA  = Ag + (size_t)(m0 + row) * 1024 + half * 32;
    const __half* srcBh = Wh + (size_t)(n0 + row) * 1024 + half * 32;
    const __half* srcBl = Wl + (size_t)(n0 + row) * 1024 + half * 32;
    uint32_t rxor = (uint32_t)((row & 7) << 4);
    uint32_t dA = sb + row * 128;

    auto issue = [&](int ch) {
        uint32_t base = dA + (uint32_t)(ch & 1) * GSTG;
        const __half* sa = srcA  + ch * 64;
        const __half* sh = srcBh + ch * 64;
        const __half* sl = srcBl + ch * 64;
        #pragma unroll
        for (int j = 0; j < 4; ++j) {
            uint32_t c = (uint32_t)(half * 64 + j * 16) ^ rxor;
            CP16(base + c,         sa + j * 8);
            CP16(base + 16384 + c, sh + j * 8);
            CP16(base + 32768 + c, sl + j * 8);
        }
    };

    float c[4][4][4] = {};
    uint32_t x = (uint32_t)((lane & 7) << 4);
    uint32_t arowb = (uint32_t)((wm * 64 + (lane & 15)) * 128);
    uint32_t acol = (uint32_t)((lane >> 4) << 4);
    uint32_t browb = (uint32_t)((wn * 32 + (lane & 7) + ((lane >> 4) << 3)) * 128);
    uint32_t bcol = (uint32_t)(((lane >> 3) & 1) << 4);

    issue(0); CP_COMMIT();

    for (int it = 0; it < GNIT; ++it) {
        CP_WAIT(0);
        __syncthreads();
        if (it + 1 < GNIT) { issue(it + 1); CP_COMMIT(); }

        uint32_t Abase  = sb + (uint32_t)(it & 1) * GSTG;
        uint32_t Bhbase = Abase + 16384;
        uint32_t Blbase = Abase + 32768;
        #pragma unroll
        for (int kt = 0; kt < 4; ++kt) {
            uint32_t ac = ((uint32_t)(kt * 32) + acol) ^ x;
            uint32_t af[4][4];
            #pragma unroll
            for (int mi = 0; mi < 4; ++mi)
                ldm_x4(af[mi], Abase + arowb + mi * 16 * 128 + ac);
            uint32_t bc = ((uint32_t)(kt * 32) + bcol) ^ x;
            #pragma unroll
            for (int nip = 0; nip < 2; ++nip) {
                uint32_t baddr = browb + nip * 16 * 128 + bc;
                uint32_t bh4[4], bl4[4];
                ldm_x4(bh4, Bhbase + baddr);
                ldm_x4(bl4, Blbase + baddr);
                #pragma unroll
                for (int mi = 0; mi < 4; ++mi) {
                    mma16816(c[mi][2*nip],   af[mi], bh4);
                    mma16816(c[mi][2*nip],   af[mi], bl4);
                    mma16816(c[mi][2*nip+1], af[mi], bh4 + 2);
                    mma16816(c[mi][2*nip+1], af[mi], bl4 + 2);
                }
            }
        }
    }

    // epilogue
    int g = lane >> 2, cq = (lane & 3) * 2;
    #pragma unroll
    for (int mi = 0; mi < 4; ++mi) {
        int r0 = m0 + wm*64 + mi*16 + g;
        int r1 = r0 + 8;
        #pragma unroll
        for (int ni = 0; ni < 4; ++ni) {
            int col = n0 + wn*32 + ni*8 + cq;
            float b0v = __ldg(bias + col), b1v = __ldg(bias + col + 1);
            float v00 = c[mi][ni][0] + b0v, v01 = c[mi][ni][1] + b1v;
            float v10 = c[mi][ni][2] + b0v, v11 = c[mi][ni][3] + b1v;
            if (SPLIT) {
                int hh = col >> 6, hd = col & 63;
                int bi0 = r0 >> 11, s0 = r0 & 2047;
                int bi1 = r1 >> 11, s1 = r1 & 2047;
                size_t i0 = ((((size_t)bi0*NHEAD + hh)*SEQ) + s0)*HDIM + hd;
                size_t i1 = ((((size_t)bi1*NHEAD + hh)*SEQ) + s1)*HDIM + hd;
                __half2 h0 = __floats2half2_rn(v00, v01);
                __half2 h1 = __floats2half2_rn(v10, v11);
                *(__half2*)(Ch + i0) = h0;
                *(__half2*)(Ch + i1) = h1;
                if (Cl) {
                    __half2 l0 = __floats2half2_rn(v00 - __half2float(__low2half(h0)),
                                                   v01 - __half2float(__high2half(h0)));
                    __half2 l1 = __floats2half2_rn(v10 - __half2float(__low2half(h1)),
                                                   v11 - __half2float(__high2half(h1)));
                    *(__half2*)(Cl + i0) = l0;
                    *(__half2*)(Cl + i1) = l1;
                }
            } else {
                float2 v0 = {v00, v01}, v1 = {v10, v11};
                *(float2*)&Cf[(size_t)r0*DMODEL + col] = v0;
                *(float2*)&Cf[(size_t)r1*DMODEL + col] = v1;
            }
        }
    }
}

// ---------------- Flash attention (fp16; K hi+lo, V hi-only) ----------------
// grid (SEQ/128, B*H), 256 threads. Warp w owns query rows [w*16, w*16+16).
// Stage = {Kh 8K, Kl 8K, Vh 8K} = 24KB; 2 stages + masks. PV uses Vh only.
#define ASTG 24576
#define KM_OFF (2*ASTG)
#define ATTN_SMEM (KM_OFF + 2*64*4)

__global__ __launch_bounds__(256, 2) void attn_cp_kernel(
    const __half* __restrict__ qhh,
    const __half* __restrict__ khh, const __half* __restrict__ khl,
    const __half* __restrict__ vhh,
    __half* __restrict__ obh)
{
    extern __shared__ __align__(128) unsigned char smraw[];
    float* kmf = (float*)(smraw + KM_OFF);

    int t = threadIdx.x, lane = t & 31, w = t >> 5;
    int g = lane >> 2, cq = (lane & 3) * 2;
    int qt = blockIdx.x, bh = blockIdx.y;
    int b = bh >> 4, h = bh & 15;
    int q0 = qt * 128;
    size_t bhoff = (size_t)bh * SEQ * HDIM;
    const __half* qb = qhh + bhoff + (size_t)q0 * HDIM;
    const unsigned char* mb = g_mask + b * SEQ;

    uint32_t sbse = (uint32_t)__cvta_generic_to_shared(smraw);
    uint32_t x = (uint32_t)((lane & 7) << 4);

    // KV loading: 256 threads, each covers 32B of one row per region (3 regions)
    int rowq = t >> 2, part = t & 3;
    uint32_t rxq = (uint32_t)((rowq & 7) << 4);
    const __half* kvsrc[3] = {
        khh + bhoff + (size_t)rowq * HDIM + part * 16,
        khl + bhoff + (size_t)rowq * HDIM + part * 16,
        vhh + bhoff + (size_t)rowq * HDIM + part * 16 };

    auto issueKV = [&](int it2) {
        int st = it2 & 1;
        uint32_t base = sbse + st * ASTG + rowq * 128;
        size_t koff = (size_t)it2 * 64 * HDIM;
        #pragma unroll
        for (int rgn = 0; rgn < 3; ++rgn) {
            const __half* src = kvsrc[rgn] + koff;
            uint32_t db = base + rgn * 8192;
            #pragma unroll
            for (int j = 0; j < 2; ++j) {
                uint32_t c = (uint32_t)(part * 32 + j * 16) ^ rxq;
                CP16(db + c, src + j * 8);
            }
        }
        if (t < 64) kmf[st*64 + t] = mb[it2*64 + t] ? 0.0f : NEG_INF;
    };

    issueKV(0); CP_COMMIT();

    // stage Q (hi, 128 rows x 128B = 16KB) through stage-1 buffer (24KB)
    {
        int rq = t >> 1, hq = t & 1;
        uint32_t qdst = sbse + ASTG + rq * 128;
        const uint4* gq = (const uint4*)(qb + rq * HDIM + hq * 32);
        uint32_t rx = (uint32_t)((rq & 7) << 4);
        #pragma unroll
        for (int j = 0; j < 4; ++j) {
            uint32_t c = (uint32_t)(hq * 64 + j * 16) ^ rx;
            uint4 v = gq[j];
            asm volatile("st.shared.v4.b32 [%0], {%1,%2,%3,%4};" ::
                "r"(qdst + c), "r"(v.x), "r"(v.y), "r"(v.z), "r"(v.w));
        }
    }
    __syncthreads();
    uint32_t qf[4][4];
    {
        uint32_t qrow = (uint32_t)(w*16 + (lane & 15));
        uint32_t qc = (uint32_t)((lane >> 4) << 4);
        #pragma unroll
        for (int kt = 0; kt < 4; ++kt) {
            uint32_t c = ((uint32_t)(kt*32) + qc) ^ x;
            ldm_x4(qf[kt], sbse + ASTG + qrow * 128 + c);
        }
    }
    __syncthreads();            // all warps have Q frags; stage 1 reusable

    float oc[8][4] = {};
    float m0r = NEG_INF, m1r = NEG_INF, l0r = 0.f, l1r = 0.f;
    uint32_t krow = (uint32_t)(lane & 7);
    uint32_t kq16 = (uint32_t)((lane >> 3) << 4);
    uint32_t vlr = (uint32_t)(lane & 15);
    uint32_t vsel = (uint32_t)((lane >> 4) << 4);
    const float SC2 = 0.125f * LOG2E;

    const int NT = SEQ / 64;   // 32
    for (int it = 0; it < NT; ++it) {
        CP_WAIT(0);
        __syncthreads();     // stage it visible; all warps done with it-1
        if (it + 1 < NT) { issueKV(it + 1); CP_COMMIT(); }

        uint32_t stage = sbse + (uint32_t)(it & 1) * ASTG;
        const uint32_t KhB = stage, KlB = stage + 8192;
        const uint32_t VhB = stage + 16384;
        const float* km = kmf + (it & 1) * 64;

        // S = Qh Kh^T + Qh Kl^T  (16 rows x 64 keys per warp)
        float sc[8][4] = {};
        #pragma unroll
        for (int nt = 0; nt < 8; ++nt) {
            uint32_t rbase = ((uint32_t)(nt*8) + krow) * 128;
            #pragma unroll
            for (int ktp = 0; ktp < 2; ++ktp) {
                uint32_t c = ((uint32_t)(ktp*64) + kq16) ^ x;
                uint32_t kh4[4], kl4[4];
                ldm_x4(kh4, KhB + rbase + c);
                ldm_x4(kl4, KlB + rbase + c);
                mma16816(sc[nt], qf[2*ktp],   kh4);
                mma16816(sc[nt], qf[2*ktp],   kl4);
                mma16816(sc[nt], qf[2*ktp+1], kh4 + 2);
                mma16816(sc[nt], qf[2*ktp+1], kl4 + 2);
            }
        }

        // online softmax in exp2 domain
        float r0m = NEG_INF, r1m = NEG_INF;
        #pragma unroll
        for (int nt = 0; nt < 8; ++nt) {
            float a0 = km[nt*8 + cq], a1 = km[nt*8 + cq + 1];
            sc[nt][0] = sc[nt][0]*SC2 + a0;
            sc[nt][1] = sc[nt][1]*SC2 + a1;
            sc[nt][2] = sc[nt][2]*SC2 + a0;
            sc[nt][3] = sc[nt][3]*SC2 + a1;
            r0m = fmaxf(r0m, fmaxf(sc[nt][0], sc[nt][1]));
            r1m = fmaxf(r1m, fmaxf(sc[nt][2], sc[nt][3]));
        }
        r0m = fmaxf(r0m, __shfl_xor_sync(0xffffffffu, r0m, 1));
        r0m = fmaxf(r0m, __shfl_xor_sync(0xffffffffu, r0m, 2));
        r1m = fmaxf(r1m, __shfl_xor_sync(0xffffffffu, r1m, 1));
        r1m = fmaxf(r1m, __shfl_xor_sync(0xffffffffu, r1m, 2));
        float mn0 = fmaxf(m0r, r0m), mn1 = fmaxf(m1r, r1m);
        float ms0 = (mn0 == NEG_INF) ? 0.0f : mn0;
        float ms1 = (mn1 == NEG_INF) ? 0.0f : mn1;
        float al0 = exp2f(m0r - ms0), al1 = exp2f(m1r - ms1);
        m0r = mn0; m1r = mn1;

        // exp2 + pack P (fp16 hi) directly into PV A-fragment registers
        uint32_t ph[8], ph2[8];
        float rs0 = 0.f, rs1 = 0.f;
        #pragma unroll
        for (int nt = 0; nt < 8; ++nt) {
            float p0 = exp2f(sc[nt][0] - ms0), p1 = exp2f(sc[nt][1] - ms0);
            float p2 = exp2f(sc[nt][2] - ms1), p3 = exp2f(sc[nt][3] - ms1);
            rs0 += p0 + p1; rs1 += p2 + p3;
            __half2 hv0 = __floats2half2_rn(p0, p1);
            __half2 hv1 = __floats2half2_rn(p2, p3);
            ph[nt]  = *(uint32_t*)&hv0;
            ph2[nt] = *(uint32_t*)&hv1;
        }
        rs0 += __shfl_xor_sync(0xffffffffu, rs0, 1);
        rs0 += __shfl_xor_sync(0xffffffffu, rs0, 2);
        rs1 += __shfl_xor_sync(0xffffffffu, rs1, 1);
        rs1 += __shfl_xor_sync(0xffffffffu, rs1, 2);
        l0r = l0r * al0 + rs0;
        l1r = l1r * al1 + rs1;
        #pragma unroll
        for (int nt = 0; nt < 8; ++nt) {
            oc[nt][0] *= al0; oc[nt][1] *= al0;
            oc[nt][2] *= al1; oc[nt][3] *= al1;
        }

        // O += Ph Vh  (V hi only)
        #pragma unroll
        for (int kt = 0; kt < 4; ++kt) {
            uint32_t pa[4] = {ph[2*kt], ph2[2*kt], ph[2*kt+1], ph2[2*kt+1]};
            uint32_t vr = ((uint32_t)(kt*16) + vlr) * 128;
            #pragma unroll
            for (int ntp = 0; ntp < 4; ++ntp) {
                uint32_t c = ((uint32_t)(ntp*32) + vsel) ^ x;
                uint32_t vh4[4];
                ldm_x4t(vh4, VhB + vr + c);
                mma16816(oc[2*ntp],   pa, vh4);
                mma16816(oc[2*ntp+1], pa, vh4 + 2);
            }
        }
    }

    // epilogue: normalize, zero masked query rows, write (b,s,d) as fp16 hi
    int r0 = w*16 + g, r1 = r0 + 8;
    float inv0 = (mb[q0 + r0] && l0r > 0.f) ? 1.0f / l0r : 0.0f;
    float inv1 = (mb[q0 + r1] && l1r > 0.f) ? 1.0f / l1r : 0.0f;
    size_t base0 = ((size_t)b*SEQ + q0 + r0)*DMODEL + h*HDIM;
    size_t base1 = ((size_t)b*SEQ + q0 + r1)*DMODEL + h*HDIM;
    #pragma unroll
    for (int nt = 0; nt < 8; ++nt) {
        __half2 h0 = __floats2half2_rn(oc[nt][0]*inv0, oc[nt][1]*inv0);
        __half2 h1 = __floats2half2_rn(oc[nt][2]*inv1, oc[nt][3]*inv1);
        *(__half2*)(obh + base0 + nt*8 + cq) = h0;
        *(__half2*)(obh + base1 + nt*8 + cq) = h1;
    }
}

// ---------------- launch ----------------------------------------------------
extern "C" void kernel_launch(void* const* d_in, const int* in_sizes, int n_in,
                              void* d_out, int out_size) {
    const float* q    = (const float*)d_in[0];
    const unsigned char* mask = (const unsigned char*)d_in[1];
    const float* Wq   = (const float*)d_in[2];
    const float* bq   = (const float*)d_in[3];
    const float* Wk   = (const float*)d_in[4];
    const float* bk   = (const float*)d_in[5];
    const float* Wv   = (const float*)d_in[6];
    const float* bv   = (const float*)d_in[7];
    const float* Wo   = (const float*)d_in[8];
    const float* bo   = (const float*)d_in[9];
    float* out = (float*)d_out;

    __half *ah, *wh, *wl, *qhh, *khh, *khl, *vhh, *oh;
    cudaGetSymbolAddress((void**)&ah,  g_ah);
    cudaGetSymbolAddress((void**)&wh,  g_wh);
    cudaGetSymbolAddress((void**)&wl,  g_wl);
    cudaGetSymbolAddress((void**)&qhh, g_qhh);
    cudaGetSymbolAddress((void**)&khh, g_khh);
    cudaGetSymbolAddress((void**)&khl, g_khl);
    cudaGetSymbolAddress((void**)&vhh, g_vhh);
    cudaGetSymbolAddress((void**)&oh,  g_oh);

    detect_mask_kernel<<<1, 256>>>(mask);
    convert_mask_kernel<<<(BATCH*SEQ + 255) / 256, 256>>>(mask);

    tohalf_kernel<<<NELEM / 1024, 256>>>(q, ah, NELEM);
    split_w_kernel<<<dim3(1024, 1, 4), 256>>>(Wq, Wk, Wv, Wo, wh, wl);

    const int gemm_smem = 2 * GSTG;   // 98304 B -> 2 CTAs/SM
    static bool attr_done = false;
    if (!attr_done) {
        cudaFuncSetAttribute(gemm_cp_kernel<true>,
                             cudaFuncAttributeMaxDynamicSharedMemorySize, gemm_smem);
        cudaFuncSetAttribute(gemm_cp_kernel<false>,
                             cudaFuncAttributeMaxDynamicSharedMemorySize, gemm_smem);
        cudaFuncSetAttribute(attn_cp_kernel,
                             cudaFuncAttributeMaxDynamicSharedMemorySize, ATTN_SMEM);
        attr_done = true;
    }

    // fused QKV projections (Q -> hi; K -> hi+lo; V -> hi only)
    gemm_cp_kernel<true><<<dim3(8, 64, 3), 256, gemm_smem>>>(
        ah, wh, wl, 0, bq, bk, bv,
        qhh, nullptr, khh, khl, vhh, nullptr, nullptr);

    attn_cp_kernel<<<dim3(SEQ / 128, BATCH * NHEAD), 256, ATTN_SMEM>>>(
        qhh, khh, khl, vhh, oh);

    // output projection -> fp32 out
    gemm_cp_kernel<false><<<dim3(8, 64, 1), 256, gemm_smem>>>(
        oh, wh, wl, 3, bo, bo, bo,
        nullptr, nullptr, nullptr, nullptr, nullptr, nullptr, out);
}

// round 16
// speedup vs baseline: 1.2528x; 1.1174x over previous
#include <cuda_runtime.h>
#include <cuda_fp16.h>
#include <cstdint>

// Problem constants
#define BATCH 4
#define SEQ   2048
#define DMODEL 1024
#define NHEAD 16
#define HDIM  64
#define MROWS (BATCH*SEQ)         // 8192

#define NEG_INF __int_as_float(0xff800000)
#define LOG2E 1.44269504f

// ---------------- scratch (device globals; no allocation allowed) ----------
#define NELEM (8192*1024)
__device__ __half g_ah[NELEM];                            // input x, fp16 hi only
__device__ __half g_wh[4*1024*1024], g_wl[4*1024*1024];   // Wq,Wk,Wv,Wo hi/lo
__device__ __half g_qhh[NELEM];                           // Q heads hi only
__device__ __half g_khh[NELEM];                           // K heads hi only
__device__ __half g_vhh[NELEM];                           // V heads hi only
__device__ __half g_oh[NELEM];                            // attn out hi only
__device__ unsigned char g_mask[BATCH*SEQ];
__device__ int g_mode;

// ---------------- mask dtype detection + canonicalization ------------------
__global__ void detect_mask_kernel(const unsigned char* __restrict__ p) {
    __shared__ int s1, s3;
    if (threadIdx.x == 0) { s1 = 0; s3 = 0; }
    __syncthreads();
    int l1 = 0, l3 = 0;
    for (int i = threadIdx.x; i < BATCH*SEQ; i += blockDim.x) {
        unsigned char v = p[i];
        int m = i & 3;
        if (m == 1 && v) l1 = 1;
        if (m == 3 && v) l3 = 1;
    }
    if (l1) atomicOr(&s1, 1);
    if (l3) atomicOr(&s3, 1);
    __syncthreads();
    if (threadIdx.x == 0) g_mode = s1 ? 0 : (s3 ? 1 : 2);  // 0=u8, 1=f32, 2=i32
}

__global__ void convert_mask_kernel(const unsigned char* __restrict__ p) {
    int i = blockIdx.x * blockDim.x + threadIdx.x;
    if (i >= BATCH*SEQ) return;
    int mode = g_mode;
    unsigned char r;
    if (mode == 0)      r = (p[i] != 0);
    else if (mode == 1) r = (((const float*)p)[i] != 0.0f);
    else                r = (((const int*)p)[i] != 0);
    g_mask[i] = r;
}

// ---------------- fp32 -> fp16 conversion kernels ---------------------------
__global__ void tohalf_kernel(const float* __restrict__ src,
                              __half* __restrict__ hi, int n) {
    int i = (blockIdx.x * blockDim.x + threadIdx.x) * 4;
    if (i >= n) return;
    float4 v = *(const float4*)(src + i);
    *(__half2*)(hi + i)     = __floats2half2_rn(v.x, v.y);
    *(__half2*)(hi + i + 2) = __floats2half2_rn(v.z, v.w);
}

__global__ void split_w_kernel(const float* __restrict__ w0, const float* __restrict__ w1,
                               const float* __restrict__ w2, const float* __restrict__ w3,
                               __half* __restrict__ hi, __half* __restrict__ lo) {
    int z = blockIdx.z;
    const float* src = (z==0)?w0:(z==1)?w1:(z==2)?w2:w3;
    size_t off = (size_t)z * 1024 * 1024;
    int i = (blockIdx.x * blockDim.x + threadIdx.x) * 4;
    float4 v = *(const float4*)(src + i);
    float f[4] = {v.x, v.y, v.z, v.w};
    __half h[4], l[4];
    #pragma unroll
    for (int j = 0; j < 4; ++j) {
        h[j] = __float2half_rn(f[j]);
        l[j] = __float2half_rn(f[j] - __half2float(h[j]));
    }
    *(__half2*)(hi + off + i)     = __halves2half2(h[0], h[1]);
    *(__half2*)(hi + off + i + 2) = __halves2half2(h[2], h[3]);
    *(__half2*)(lo + off + i)     = __halves2half2(l[0], l[1]);
    *(__half2*)(lo + off + i + 2) = __halves2half2(l[2], l[3]);
}

// ---------------- mma / ldmatrix / cp.async primitives ----------------------
__device__ __forceinline__ void mma16816(float* c, const uint32_t* a, const uint32_t* b) {
    asm volatile(
        "mma.sync.aligned.m16n8k16.row.col.f32.f16.f16.f32 "
        "{%0,%1,%2,%3}, {%4,%5,%6,%7}, {%8,%9}, {%0,%1,%2,%3};"
        : "+f"(c[0]), "+f"(c[1]), "+f"(c[2]), "+f"(c[3])
        : "r"(a[0]), "r"(a[1]), "r"(a[2]), "r"(a[3]), "r"(b[0]), "r"(b[1]));
}
__device__ __forceinline__ void ldm_x4(uint32_t* r, uint32_t addr) {
    asm volatile("ldmatrix.sync.aligned.m8n8.x4.shared.b16 {%0,%1,%2,%3}, [%4];"
                 : "=r"(r[0]), "=r"(r[1]), "=r"(r[2]), "=r"(r[3]) : "r"(addr));
}
__device__ __forceinline__ void ldm_x4t(uint32_t* r, uint32_t addr) {
    asm volatile("ldmatrix.sync.aligned.m8n8.x4.trans.shared.b16 {%0,%1,%2,%3}, [%4];"
                 : "=r"(r[0]), "=r"(r[1]), "=r"(r[2]), "=r"(r[3]) : "r"(addr));
}
#define CP16(dst, src) \
    asm volatile("cp.async.cg.shared.global [%0], [%1], 16;" :: "r"(dst), "l"(src))
#define CP_COMMIT() asm volatile("cp.async.commit_group;" ::: "memory")
#define CP_WAIT(n)  asm volatile("cp.async.wait_group %0;" :: "n"(n) : "memory")

// ---------------- GEMM: C = A @ W^T + bias (fp16x2, 2-stage, occ 2) ---------
#define GSTG 49152
#define GNIT 16

template <bool SPLIT>
__global__ __launch_bounds__(256, 2) void gemm_cp_kernel(
    const __half* __restrict__ Ag,
    const __half* __restrict__ Whb, const __half* __restrict__ Wlb, int woff,
    const float* b0, const float* b1, const float* b2,
    __half* C0h, __half* C0l,
    __half* C1h, __half* C1l,
    __half* C2h, __half* C2l,
    float* Cf)
{
    int z = blockIdx.z;
    const __half* Wh = Whb + (size_t)(woff + z) * 1024 * 1024;
    const __half* Wl = Wlb + (size_t)(woff + z) * 1024 * 1024;
    const float* bias = (z == 0) ? b0 : (z == 1) ? b1 : b2;
    __half* Ch = (z == 0) ? C0h : (z == 1) ? C1h : C2h;
    __half* Cl = (z == 0) ? C0l : (z == 1) ? C1l : C2l;

    extern __shared__ __align__(128) unsigned char smraw[];
    uint32_t sb = (uint32_t)__cvta_generic_to_shared(smraw);

    int t = threadIdx.x, lane = t & 31, warp = t >> 5;
    int wm = warp >> 2, wn = warp & 3;
    int m0 = blockIdx.y * 128, n0 = blockIdx.x * 128;

    int row = t >> 1, half = t & 1;
    const __half* srcA  = Ag + (size_t)(m0 + row) * 1024 + half * 32;
    const __half* srcBh = Wh + (size_t)(n0 + row) * 1024 + half * 32;
    const __half* srcBl = Wl + (size_t)(n0 + row) * 1024 + half * 32;
    uint32_t rxor = (uint32_t)((row & 7) << 4);
    uint32_t dA = sb + row * 128;

    auto issue = [&](int ch) {
        uint32_t base = dA + (uint32_t)(ch & 1) * GSTG;
        const __half* sa = srcA  + ch * 64;
        const __half* sh = srcBh + ch * 64;
        const __half* sl = srcBl + ch * 64;
        #pragma unroll
        for (int j = 0; j < 4; ++j) {
            uint32_t c = (uint32_t)(half * 64 + j * 16) ^ rxor;
            CP16(base + c,         sa + j * 8);
            CP16(base + 16384 + c, sh + j * 8);
            CP16(base + 32768 + c, sl + j * 8);
        }
    };

    float c[4][4][4] = {};
    uint32_t x = (uint32_t)((lane & 7) << 4);
    uint32_t arowb = (uint32_t)((wm * 64 + (lane & 15)) * 128);
    uint32_t acol = (uint32_t)((lane >> 4) << 4);
    uint32_t browb = (uint32_t)((wn * 32 + (lane & 7) + ((lane >> 4) << 3)) * 128);
    uint32_t bcol = (uint32_t)(((lane >> 3) & 1) << 4);

    issue(0); CP_COMMIT();

    for (int it = 0; it < GNIT; ++it) {
        CP_WAIT(0);
        __syncthreads();
        if (it + 1 < GNIT) { issue(it + 1); CP_COMMIT(); }

        uint32_t Abase  = sb + (uint32_t)(it & 1) * GSTG;
        uint32_t Bhbase = Abase + 16384;
        uint32_t Blbase = Abase + 32768;
        #pragma unroll
        for (int kt = 0; kt < 4; ++kt) {
            uint32_t ac = ((uint32_t)(kt * 32) + acol) ^ x;
            uint32_t af[4][4];
            #pragma unroll
            for (int mi = 0; mi < 4; ++mi)
                ldm_x4(af[mi], Abase + arowb + mi * 16 * 128 + ac);
            uint32_t bc = ((uint32_t)(kt * 32) + bcol) ^ x;
            #pragma unroll
            for (int nip = 0; nip < 2; ++nip) {
                uint32_t baddr = browb + nip * 16 * 128 + bc;
                uint32_t bh4[4], bl4[4];
                ldm_x4(bh4, Bhbase + baddr);
                ldm_x4(bl4, Blbase + baddr);
                #pragma unroll
                for (int mi = 0; mi < 4; ++mi) {
                    mma16816(c[mi][2*nip],   af[mi], bh4);
                    mma16816(c[mi][2*nip],   af[mi], bl4);
                    mma16816(c[mi][2*nip+1], af[mi], bh4 + 2);
                    mma16816(c[mi][2*nip+1], af[mi], bl4 + 2);
                }
            }
        }
    }

    // epilogue
    int g = lane >> 2, cq = (lane & 3) * 2;
    #pragma unroll
    for (int mi = 0; mi < 4; ++mi) {
        int r0 = m0 + wm*64 + mi*16 + g;
        int r1 = r0 + 8;
        #pragma unroll
        for (int ni = 0; ni < 4; ++ni) {
            int col = n0 + wn*32 + ni*8 + cq;
            float b0v = __ldg(bias + col), b1v = __ldg(bias + col + 1);
            float v00 = c[mi][ni][0] + b0v, v01 = c[mi][ni][1] + b1v;
            float v10 = c[mi][ni][2] + b0v, v11 = c[mi][ni][3] + b1v;
            if (SPLIT) {
                int hh = col >> 6, hd = col & 63;
                int bi0 = r0 >> 11, s0 = r0 & 2047;
                int bi1 = r1 >> 11, s1 = r1 & 2047;
                size_t i0 = ((((size_t)bi0*NHEAD + hh)*SEQ) + s0)*HDIM + hd;
                size_t i1 = ((((size_t)bi1*NHEAD + hh)*SEQ) + s1)*HDIM + hd;
                __half2 h0 = __floats2half2_rn(v00, v01);
                __half2 h1 = __floats2half2_rn(v10, v11);
                *(__half2*)(Ch + i0) = h0;
                *(__half2*)(Ch + i1) = h1;
                if (Cl) {
                    __half2 l0 = __floats2half2_rn(v00 - __half2float(__low2half(h0)),
                                                   v01 - __half2float(__high2half(h0)));
                    __half2 l1 = __floats2half2_rn(v10 - __half2float(__low2half(h1)),
                                                   v11 - __half2float(__high2half(h1)));
                    *(__half2*)(Cl + i0) = l0;
                    *(__half2*)(Cl + i1) = l1;
                }
            } else {
                float2 v0 = {v00, v01}, v1 = {v10, v11};
                *(float2*)&Cf[(size_t)r0*DMODEL + col] = v0;
                *(float2*)&Cf[(size_t)r1*DMODEL + col] = v1;
            }
        }
    }
}

// ---------------- Flash attention (pure fp16 QK/PV, hi operands) ------------
// grid (SEQ/128, B*H), 256 threads. Warp w owns query rows [w*16, w*16+16).
// Stage = {Kh 8K, Vh 8K} = 16KB; 2 stages + masks. S = Qh*Kh; O += Ph*Vh.
#define ASTG 16384
#define KM_OFF (2*ASTG)
#define ATTN_SMEM (KM_OFF + 2*64*4)

__global__ __launch_bounds__(256, 2) void attn_cp_kernel(
    const __half* __restrict__ qhh,
    const __half* __restrict__ khh,
    const __half* __restrict__ vhh,
    __half* __restrict__ obh)
{
    extern __shared__ __align__(128) unsigned char smraw[];
    float* kmf = (float*)(smraw + KM_OFF);

    int t = threadIdx.x, lane = t & 31, w = t >> 5;
    int g = lane >> 2, cq = (lane & 3) * 2;
    int qt = blockIdx.x, bh = blockIdx.y;
    int b = bh >> 4, h = bh & 15;
    int q0 = qt * 128;
    size_t bhoff = (size_t)bh * SEQ * HDIM;
    const __half* qb = qhh + bhoff + (size_t)q0 * HDIM;
    const unsigned char* mb = g_mask + b * SEQ;

    uint32_t sbse = (uint32_t)__cvta_generic_to_shared(smraw);
    uint32_t x = (uint32_t)((lane & 7) << 4);

    // KV loading: 256 threads, each covers 32B of one row per region (2 regions)
    int rowq = t >> 2, part = t & 3;
    uint32_t rxq = (uint32_t)((rowq & 7) << 4);
    const __half* kvsrc[2] = {
        khh + bhoff + (size_t)rowq * HDIM + part * 16,
        vhh + bhoff + (size_t)rowq * HDIM + part * 16 };

    auto issueKV = [&](int it2) {
        int st = it2 & 1;
        uint32_t base = sbse + st * ASTG + rowq * 128;
        size_t koff = (size_t)it2 * 64 * HDIM;
        #pragma unroll
        for (int rgn = 0; rgn < 2; ++rgn) {
            const __half* src = kvsrc[rgn] + koff;
            uint32_t db = base + rgn * 8192;
            #pragma unroll
            for (int j = 0; j < 2; ++j) {
                uint32_t c = (uint32_t)(part * 32 + j * 16) ^ rxq;
                CP16(db + c, src + j * 8);
            }
        }
        if (t < 64) kmf[st*64 + t] = mb[it2*64 + t] ? 0.0f : NEG_INF;
    };

    issueKV(0); CP_COMMIT();

    // stage Q (hi, 128 rows x 128B = 16KB) through stage-1 buffer (16KB)
    {
        int rq = t >> 1, hq = t & 1;
        uint32_t qdst = sbse + ASTG + rq * 128;
        const uint4* gq = (const uint4*)(qb + rq * HDIM + hq * 32);
        uint32_t rx = (uint32_t)((rq & 7) << 4);
        #pragma unroll
        for (int j = 0; j < 4; ++j) {
            uint32_t c = (uint32_t)(hq * 64 + j * 16) ^ rx;
            uint4 v = gq[j];
            asm volatile("st.shared.v4.b32 [%0], {%1,%2,%3,%4};" ::
                "r"(qdst + c), "r"(v.x), "r"(v.y), "r"(v.z), "r"(v.w));
        }
    }
    __syncthreads();
    uint32_t qf[4][4];
    {
        uint32_t qrow = (uint32_t)(w*16 + (lane & 15));
        uint32_t qc = (uint32_t)((lane >> 4) << 4);
        #pragma unroll
        for (int kt = 0; kt < 4; ++kt) {
            uint32_t c = ((uint32_t)(kt*32) + qc) ^ x;
            ldm_x4(qf[kt], sbse + ASTG + qrow * 128 + c);
        }
    }
    __syncthreads();            // all warps have Q frags; stage 1 reusable

    float oc[8][4] = {};
    float m0r = NEG_INF, m1r = NEG_INF, l0r = 0.f, l1r = 0.f;
    uint32_t krow = (uint32_t)(lane & 7);
    uint32_t kq16 = (uint32_t)((lane >> 3) << 4);
    uint32_t vlr = (uint32_t)(lane & 15);
    uint32_t vsel = (uint32_t)((lane >> 4) << 4);
    const float SC2 = 0.125f * LOG2E;

    const int NT = SEQ / 64;   // 32
    for (int it = 0; it < NT; ++it) {
        CP_WAIT(0);
        __syncthreads();     // stage it visible; all warps done with it-1
        if (it + 1 < NT) { issueKV(it + 1); CP_COMMIT(); }

        uint32_t stage = sbse + (uint32_t)(it & 1) * ASTG;
        const uint32_t KhB = stage;
        const uint32_t VhB = stage + 8192;
        const float* km = kmf + (it & 1) * 64;

        // S = Qh Kh^T  (16 rows x 64 keys per warp)
        float sc[8][4] = {};
        #pragma unroll
        for (int nt = 0; nt < 8; ++nt) {
            uint32_t rbase = ((uint32_t)(nt*8) + krow) * 128;
            #pragma unroll
            for (int ktp = 0; ktp < 2; ++ktp) {
                uint32_t c = ((uint32_t)(ktp*64) + kq16) ^ x;
                uint32_t kh4[4];
                ldm_x4(kh4, KhB + rbase + c);
                mma16816(sc[nt], qf[2*ktp],   kh4);
                mma16816(sc[nt], qf[2*ktp+1], kh4 + 2);
            }
        }

        // online softmax in exp2 domain
        float r0m = NEG_INF, r1m = NEG_INF;
        #pragma unroll
        for (int nt = 0; nt < 8; ++nt) {
            float a0 = km[nt*8 + cq], a1 = km[nt*8 + cq + 1];
            sc[nt][0] = sc[nt][0]*SC2 + a0;
            sc[nt][1] = sc[nt][1]*SC2 + a1;
            sc[nt][2] = sc[nt][2]*SC2 + a0;
            sc[nt][3] = sc[nt][3]*SC2 + a1;
            r0m = fmaxf(r0m, fmaxf(sc[nt][0], sc[nt][1]));
            r1m = fmaxf(r1m, fmaxf(sc[nt][2], sc[nt][3]));
        }
        r0m = fmaxf(r0m, __shfl_xor_sync(0xffffffffu, r0m, 1));
        r0m = fmaxf(r0m, __shfl_xor_sync(0xffffffffu, r0m, 2));
        r1m = fmaxf(r1m, __shfl_xor_sync(0xffffffffu, r1m, 1));
        r1m = fmaxf(r1m, __shfl_xor_sync(0xffffffffu, r1m, 2));
        float mn0 = fmaxf(m0r, r0m), mn1 = fmaxf(m1r, r1m);
        float ms0 = (mn0 == NEG_INF) ? 0.0f : mn0;
        float ms1 = (mn1 == NEG_INF) ? 0.0f : mn1;
        float al0 = exp2f(m0r - ms0), al1 = exp2f(m1r - ms1);
        m0r = mn0; m1r = mn1;

        // exp2 + pack P (fp16 hi) directly into PV A-fragment registers
        uint32_t ph[8], ph2[8];
        float rs0 = 0.f, rs1 = 0.f;
        #pragma unroll
        for (int nt = 0; nt < 8; ++nt) {
            float p0 = exp2f(sc[nt][0] - ms0), p1 = exp2f(sc[nt][1] - ms0);
            float p2 = exp2f(sc[nt][2] - ms1), p3 = exp2f(sc[nt][3] - ms1);
            rs0 += p0 + p1; rs1 += p2 + p3;
            __half2 hv0 = __floats2half2_rn(p0, p1);
            __half2 hv1 = __floats2half2_rn(p2, p3);
            ph[nt]  = *(uint32_t*)&hv0;
            ph2[nt] = *(uint32_t*)&hv1;
        }
        rs0 += __shfl_xor_sync(0xffffffffu, rs0, 1);
        rs0 += __shfl_xor_sync(0xffffffffu, rs0, 2);
        rs1 += __shfl_xor_sync(0xffffffffu, rs1, 1);
        rs1 += __shfl_xor_sync(0xffffffffu, rs1, 2);
        l0r = l0r * al0 + rs0;
        l1r = l1r * al1 + rs1;
        #pragma unroll
        for (int nt = 0; nt < 8; ++nt) {
            oc[nt][0] *= al0; oc[nt][1] *= al0;
            oc[nt][2] *= al1; oc[nt][3] *= al1;
        }

        // O += Ph Vh
        #pragma unroll
        for (int kt = 0; kt < 4; ++kt) {
            uint32_t pa[4] = {ph[2*kt], ph2[2*kt], ph[2*kt+1], ph2[2*kt+1]};
            uint32_t vr = ((uint32_t)(kt*16) + vlr) * 128;
            #pragma unroll
            for (int ntp = 0; ntp < 4; ++ntp) {
                uint32_t c = ((uint32_t)(ntp*32) + vsel) ^ x;
                uint32_t vh4[4];
                ldm_x4t(vh4, VhB + vr + c);
                mma16816(oc[2*ntp],   pa, vh4);
                mma16816(oc[2*ntp+1], pa, vh4 + 2);
            }
        }
    }

    // epilogue: normalize, zero masked query rows, write (b,s,d) as fp16 hi
    int r0 = w*16 + g, r1 = r0 + 8;
    float inv0 = (mb[q0 + r0] && l0r > 0.f) ? 1.0f / l0r : 0.0f;
    float inv1 = (mb[q0 + r1] && l1r > 0.f) ? 1.0f / l1r : 0.0f;
    size_t base0 = ((size_t)b*SEQ + q0 + r0)*DMODEL + h*HDIM;
    size_t base1 = ((size_t)b*SEQ + q0 + r1)*DMODEL + h*HDIM;
    #pragma unroll
    for (int nt = 0; nt < 8; ++nt) {
        __half2 h0 = __floats2half2_rn(oc[nt][0]*inv0, oc[nt][1]*inv0);
        __half2 h1 = __floats2half2_rn(oc[nt][2]*inv1, oc[nt][3]*inv1);
        *(__half2*)(obh + base0 + nt*8 + cq) = h0;
        *(__half2*)(obh + base1 + nt*8 + cq) = h1;
    }
}

// ---------------- launch ----------------------------------------------------
extern "C" void kernel_launch(void* const* d_in, const int* in_sizes, int n_in,
                              void* d_out, int out_size) {
    const float* q    = (const float*)d_in[0];
    const unsigned char* mask = (const unsigned char*)d_in[1];
    const float* Wq   = (const float*)d_in[2];
    const float* bq   = (const float*)d_in[3];
    const float* Wk   = (const float*)d_in[4];
    const float* bk   = (const float*)d_in[5];
    const float* Wv   = (const float*)d_in[6];
    const float* bv   = (const float*)d_in[7];
    const float* Wo   = (const float*)d_in[8];
    const float* bo   = (const float*)d_in[9];
    float* out = (float*)d_out;

    __half *ah, *wh, *wl, *qhh, *khh, *vhh, *oh;
    cudaGetSymbolAddress((void**)&ah,  g_ah);
    cudaGetSymbolAddress((void**)&wh,  g_wh);
    cudaGetSymbolAddress((void**)&wl,  g_wl);
    cudaGetSymbolAddress((void**)&qhh, g_qhh);
    cudaGetSymbolAddress((void**)&khh, g_khh);
    cudaGetSymbolAddress((void**)&vhh, g_vhh);
    cudaGetSymbolAddress((void**)&oh,  g_oh);

    detect_mask_kernel<<<1, 256>>>(mask);
    convert_mask_kernel<<<(BATCH*SEQ + 255) / 256, 256>>>(mask);

    tohalf_kernel<<<NELEM / 1024, 256>>>(q, ah, NELEM);
    split_w_kernel<<<dim3(1024, 1, 4), 256>>>(Wq, Wk, Wv, Wo, wh, wl);

    const int gemm_smem = 2 * GSTG;   // 98304 B -> 2 CTAs/SM
    static bool attr_done = false;
    if (!attr_done) {
        cudaFuncSetAttribute(gemm_cp_kernel<true>,
                             cudaFuncAttributeMaxDynamicSharedMemorySize, gemm_smem);
        cudaFuncSetAttribute(gemm_cp_kernel<false>,
                             cudaFuncAttributeMaxDynamicSharedMemorySize, gemm_smem);
        cudaFuncSetAttribute(attn_cp_kernel,
                             cudaFuncAttributeMaxDynamicSharedMemorySize, ATTN_SMEM);
        attr_done = true;
    }

    // fused QKV projections (all heads -> fp16 hi only)
    gemm_cp_kernel<true><<<dim3(8, 64, 3), 256, gemm_smem>>>(
        ah, wh, wl, 0, bq, bk, bv,
        qhh, nullptr, khh, nullptr, vhh, nullptr, nullptr);

    attn_cp_kernel<<<dim3(SEQ / 128, BATCH * NHEAD), 256, ATTN_SMEM>>>(
        qhh, khh, vhh, oh);

    // output projection -> fp32 out
    gemm_cp_kernel<false><<<dim3(8, 64, 1), 256, gemm_smem>>>(
        oh, wh, wl, 3, bo, bo, bo,
        nullptr, nullptr, nullptr, nullptr, nullptr, nullptr, out);
}

// round 17
// speedup vs baseline: 1.4880x; 1.1878x over previous
#include <cuda_runtime.h>
#include <cuda_fp16.h>
#include <cstdint>

// Problem constants
#define BATCH 4
#define SEQ   2048
#define DMODEL 1024
#define NHEAD 16
#define HDIM  64
#define MROWS (BATCH*SEQ)         // 8192

#define NEG_INF __int_as_float(0xff800000)
#define LOG2E 1.44269504f

// ---------------- scratch (device globals; no allocation allowed) ----------
#define NELEM (8192*1024)
__device__ __half g_ah[NELEM];                            // input x, fp16 hi only
__device__ __half g_wh[4*1024*1024], g_wl[4*1024*1024];   // Wq,Wk,Wv,Wo hi/lo
__device__ __half g_qhh[NELEM];                           // Q heads hi only
__device__ __half g_khh[NELEM];                           // K heads hi only
__device__ __half g_vhh[NELEM];                           // V heads hi only
__device__ __half g_oh[NELEM];                            // attn out hi only
__device__ unsigned char g_mask[BATCH*SEQ];
__device__ int g_mode;

// ---------------- mask dtype detection + canonicalization ------------------
__global__ void detect_mask_kernel(const unsigned char* __restrict__ p) {
    __shared__ int s1, s3;
    if (threadIdx.x == 0) { s1 = 0; s3 = 0; }
    __syncthreads();
    int l1 = 0, l3 = 0;
    for (int i = threadIdx.x; i < BATCH*SEQ; i += blockDim.x) {
        unsigned char v = p[i];
        int m = i & 3;
        if (m == 1 && v) l1 = 1;
        if (m == 3 && v) l3 = 1;
    }
    if (l1) atomicOr(&s1, 1);
    if (l3) atomicOr(&s3, 1);
    __syncthreads();
    if (threadIdx.x == 0) g_mode = s1 ? 0 : (s3 ? 1 : 2);  // 0=u8, 1=f32, 2=i32
}

__global__ void convert_mask_kernel(const unsigned char* __restrict__ p) {
    int i = blockIdx.x * blockDim.x + threadIdx.x;
    if (i >= BATCH*SEQ) return;
    int mode = g_mode;
    unsigned char r;
    if (mode == 0)      r = (p[i] != 0);
    else if (mode == 1) r = (((const float*)p)[i] != 0.0f);
    else                r = (((const int*)p)[i] != 0);
    g_mask[i] = r;
}

// ---------------- fp32 -> fp16 conversion kernels ---------------------------
__global__ void tohalf_kernel(const float* __restrict__ src,
                              __half* __restrict__ hi, int n) {
    int i = (blockIdx.x * blockDim.x + threadIdx.x) * 4;
    if (i >= n) return;
    float4 v = *(const float4*)(src + i);
    *(__half2*)(hi + i)     = __floats2half2_rn(v.x, v.y);
    *(__half2*)(hi + i + 2) = __floats2half2_rn(v.z, v.w);
}

__global__ void split_w_kernel(const float* __restrict__ w0, const float* __restrict__ w1,
                               const float* __restrict__ w2, const float* __restrict__ w3,
                               __half* __restrict__ hi, __half* __restrict__ lo) {
    int z = blockIdx.z;
    const float* src = (z==0)?w0:(z==1)?w1:(z==2)?w2:w3;
    size_t off = (size_t)z * 1024 * 1024;
    int i = (blockIdx.x * blockDim.x + threadIdx.x) * 4;
    float4 v = *(const float4*)(src + i);
    float f[4] = {v.x, v.y, v.z, v.w};
    __half h[4], l[4];
    #pragma unroll
    for (int j = 0; j < 4; ++j) {
        h[j] = __float2half_rn(f[j]);
        l[j] = __float2half_rn(f[j] - __half2float(h[j]));
    }
    *(__half2*)(hi + off + i)     = __halves2half2(h[0], h[1]);
    *(__half2*)(hi + off + i + 2) = __halves2half2(h[2], h[3]);
    *(__half2*)(lo + off + i)     = __halves2half2(l[0], l[1]);
    *(__half2*)(lo + off + i + 2) = __halves2half2(l[2], l[3]);
}

// ---------------- mma / ldmatrix / cp.async primitives ----------------------
__device__ __forceinline__ void mma16816(float* c, const uint32_t* a, const uint32_t* b) {
    asm volatile(
        "mma.sync.aligned.m16n8k16.row.col.f32.f16.f16.f32 "
        "{%0,%1,%2,%3}, {%4,%5,%6,%7}, {%8,%9}, {%0,%1,%2,%3};"
        : "+f"(c[0]), "+f"(c[1]), "+f"(c[2]), "+f"(c[3])
        : "r"(a[0]), "r"(a[1]), "r"(a[2]), "r"(a[3]), "r"(b[0]), "r"(b[1]));
}
__device__ __forceinline__ void ldm_x4(uint32_t* r, uint32_t addr) {
    asm volatile("ldmatrix.sync.aligned.m8n8.x4.shared.b16 {%0,%1,%2,%3}, [%4];"
                 : "=r"(r[0]), "=r"(r[1]), "=r"(r[2]), "=r"(r[3]) : "r"(addr));
}
__device__ __forceinline__ void ldm_x4t(uint32_t* r, uint32_t addr) {
    asm volatile("ldmatrix.sync.aligned.m8n8.x4.trans.shared.b16 {%0,%1,%2,%3}, [%4];"
                 : "=r"(r[0]), "=r"(r[1]), "=r"(r[2]), "=r"(r[3]) : "r"(addr));
}
#define CP16(dst, src) \
    asm volatile("cp.async.cg.shared.global [%0], [%1], 16;" :: "r"(dst), "l"(src))
#define CP_COMMIT() asm volatile("cp.async.commit_group;" ::: "memory")
#define CP_WAIT(n)  asm volatile("cp.async.wait_group %0;" :: "n"(n) : "memory")

// ---------------- GEMM: C = A @ W^T + bias (2-stage, occ 2) -----------------
// WLO: include the Ah*Wl correction (hi+lo weights). QKV: WLO=false (W hi only,
// stage 32KB {A 16K, Bh 16K}); output proj: WLO=true (stage 48KB {A,Bh,Bl}).
#define GNIT 16

template <bool SPLIT, bool WLO>
__global__ __launch_bounds__(256, 2) void gemm_cp_kernel(
    const __half* __restrict__ Ag,
    const __half* __restrict__ Whb, const __half* __restrict__ Wlb, int woff,
    const float* b0, const float* b1, const float* b2,
    __half* C0h, __half* C1h, __half* C2h,
    float* Cf)
{
    const uint32_t STG = WLO ? 49152u : 32768u;
    int z = blockIdx.z;
    const __half* Wh = Whb + (size_t)(woff + z) * 1024 * 1024;
    const __half* Wl = Wlb + (size_t)(woff + z) * 1024 * 1024;
    const float* bias = (z == 0) ? b0 : (z == 1) ? b1 : b2;
    __half* Ch = (z == 0) ? C0h : (z == 1) ? C1h : C2h;

    extern __shared__ __align__(128) unsigned char smraw[];
    uint32_t sb = (uint32_t)__cvta_generic_to_shared(smraw);

    int t = threadIdx.x, lane = t & 31, warp = t >> 5;
    int wm = warp >> 2, wn = warp & 3;
    int m0 = blockIdx.y * 128, n0 = blockIdx.x * 128;

    int row = t >> 1, half = t & 1;
    const __half* srcA  = Ag + (size_t)(m0 + row) * 1024 + half * 32;
    const __half* srcBh = Wh + (size_t)(n0 + row) * 1024 + half * 32;
    const __half* srcBl = Wl + (size_t)(n0 + row) * 1024 + half * 32;
    uint32_t rxor = (uint32_t)((row & 7) << 4);
    uint32_t dA = sb + row * 128;

    auto issue = [&](int ch) {
        uint32_t base = dA + (uint32_t)(ch & 1) * STG;
        const __half* sa = srcA  + ch * 64;
        const __half* sh = srcBh + ch * 64;
        const __half* sl = srcBl + ch * 64;
        #pragma unroll
        for (int j = 0; j < 4; ++j) {
            uint32_t c = (uint32_t)(half * 64 + j * 16) ^ rxor;
            CP16(base + c,         sa + j * 8);
            CP16(base + 16384 + c, sh + j * 8);
            if (WLO) CP16(base + 32768 + c, sl + j * 8);
        }
    };

    float c[4][4][4] = {};
    uint32_t x = (uint32_t)((lane & 7) << 4);
    uint32_t arowb = (uint32_t)((wm * 64 + (lane & 15)) * 128);
    uint32_t acol = (uint32_t)((lane >> 4) << 4);
    uint32_t browb = (uint32_t)((wn * 32 + (lane & 7) + ((lane >> 4) << 3)) * 128);
    uint32_t bcol = (uint32_t)(((lane >> 3) & 1) << 4);

    issue(0); CP_COMMIT();

    for (int it = 0; it < GNIT; ++it) {
        CP_WAIT(0);
        __syncthreads();
        if (it + 1 < GNIT) { issue(it + 1); CP_COMMIT(); }

        uint32_t Abase  = sb + (uint32_t)(it & 1) * STG;
        uint32_t Bhbase = Abase + 16384;
        uint32_t Blbase = Abase + 32768;
        #pragma unroll
        for (int kt = 0; kt < 4; ++kt) {
            uint32_t ac = ((uint32_t)(kt * 32) + acol) ^ x;
            uint32_t af[4][4];
            #pragma unroll
            for (int mi = 0; mi < 4; ++mi)
                ldm_x4(af[mi], Abase + arowb + mi * 16 * 128 + ac);
            uint32_t bc = ((uint32_t)(kt * 32) + bcol) ^ x;
            #pragma unroll
            for (int nip = 0; nip < 2; ++nip) {
                uint32_t baddr = browb + nip * 16 * 128 + bc;
                uint32_t bh4[4];
                ldm_x4(bh4, Bhbase + baddr);
                if (WLO) {
                    uint32_t bl4[4];
                    ldm_x4(bl4, Blbase + baddr);
                    #pragma unroll
                    for (int mi = 0; mi < 4; ++mi) {
                        mma16816(c[mi][2*nip],   af[mi], bh4);
                        mma16816(c[mi][2*nip],   af[mi], bl4);
                        mma16816(c[mi][2*nip+1], af[mi], bh4 + 2);
                        mma16816(c[mi][2*nip+1], af[mi], bl4 + 2);
                    }
                } else {
                    #pragma unroll
                    for (int mi = 0; mi < 4; ++mi) {
                        mma16816(c[mi][2*nip],   af[mi], bh4);
                        mma16816(c[mi][2*nip+1], af[mi], bh4 + 2);
                    }
                }
            }
        }
    }

    // epilogue
    int g = lane >> 2, cq = (lane & 3) * 2;
    #pragma unroll
    for (int mi = 0; mi < 4; ++mi) {
        int r0 = m0 + wm*64 + mi*16 + g;
        int r1 = r0 + 8;
        #pragma unroll
        for (int ni = 0; ni < 4; ++ni) {
            int col = n0 + wn*32 + ni*8 + cq;
            float b0v = __ldg(bias + col), b1v = __ldg(bias + col + 1);
            float v00 = c[mi][ni][0] + b0v, v01 = c[mi][ni][1] + b1v;
            float v10 = c[mi][ni][2] + b0v, v11 = c[mi][ni][3] + b1v;
            if (SPLIT) {
                int hh = col >> 6, hd = col & 63;
                int bi0 = r0 >> 11, s0 = r0 & 2047;
                int bi1 = r1 >> 11, s1 = r1 & 2047;
                size_t i0 = ((((size_t)bi0*NHEAD + hh)*SEQ) + s0)*HDIM + hd;
                size_t i1 = ((((size_t)bi1*NHEAD + hh)*SEQ) + s1)*HDIM + hd;
                *(__half2*)(Ch + i0) = __floats2half2_rn(v00, v01);
                *(__half2*)(Ch + i1) = __floats2half2_rn(v10, v11);
            } else {
                float2 v0 = {v00, v01}, v1 = {v10, v11};
                *(float2*)&Cf[(size_t)r0*DMODEL + col] = v0;
                *(float2*)&Cf[(size_t)r1*DMODEL + col] = v1;
            }
        }
    }
}

// ---------------- Flash attention (pure fp16 QK/PV, hi operands) ------------
// grid (SEQ/128, B*H), 256 threads. Warp w owns query rows [w*16, w*16+16).
// Stage = {Kh 8K, Vh 8K} = 16KB; 2 stages + masks. S = Qh*Kh; O += Ph*Vh.
#define ASTG 16384
#define KM_OFF (2*ASTG)
#define ATTN_SMEM (KM_OFF + 2*64*4)

__global__ __launch_bounds__(256, 2) void attn_cp_kernel(
    const __half* __restrict__ qhh,
    const __half* __restrict__ khh,
    const __half* __restrict__ vhh,
    __half* __restrict__ obh)
{
    extern __shared__ __align__(128) unsigned char smraw[];
    float* kmf = (float*)(smraw + KM_OFF);

    int t = threadIdx.x, lane = t & 31, w = t >> 5;
    int g = lane >> 2, cq = (lane & 3) * 2;
    int qt = blockIdx.x, bh = blockIdx.y;
    int b = bh >> 4, h = bh & 15;
    int q0 = qt * 128;
    size_t bhoff = (size_t)bh * SEQ * HDIM;
    const __half* qb = qhh + bhoff + (size_t)q0 * HDIM;
    const unsigned char* mb = g_mask + b * SEQ;

    uint32_t sbse = (uint32_t)__cvta_generic_to_shared(smraw);
    uint32_t x = (uint32_t)((lane & 7) << 4);

    int rowq = t >> 2, part = t & 3;
    uint32_t rxq = (uint32_t)((rowq & 7) << 4);
    const __half* kvsrc[2] = {
        khh + bhoff + (size_t)rowq * HDIM + part * 16,
        vhh + bhoff + (size_t)rowq * HDIM + part * 16 };

    auto issueKV = [&](int it2) {
        int st = it2 & 1;
        uint32_t base = sbse + st * ASTG + rowq * 128;
        size_t koff = (size_t)it2 * 64 * HDIM;
        #pragma unroll
        for (int rgn = 0; rgn < 2; ++rgn) {
            const __half* src = kvsrc[rgn] + koff;
            uint32_t db = base + rgn * 8192;
            #pragma unroll
            for (int j = 0; j < 2; ++j) {
                uint32_t c = (uint32_t)(part * 32 + j * 16) ^ rxq;
                CP16(db + c, src + j * 8);
            }
        }
        if (t < 64) kmf[st*64 + t] = mb[it2*64 + t] ? 0.0f : NEG_INF;
    };

    issueKV(0); CP_COMMIT();

    // stage Q (hi, 128 rows x 128B = 16KB) through stage-1 buffer (16KB)
    {
        int rq = t >> 1, hq = t & 1;
        uint32_t qdst = sbse + ASTG + rq * 128;
        const uint4* gq = (const uint4*)(qb + rq * HDIM + hq * 32);
        uint32_t rx = (uint32_t)((rq & 7) << 4);
        #pragma unroll
        for (int j = 0; j < 4; ++j) {
            uint32_t c = (uint32_t)(hq * 64 + j * 16) ^ rx;
            uint4 v = gq[j];
            asm volatile("st.shared.v4.b32 [%0], {%1,%2,%3,%4};" ::
                "r"(qdst + c), "r"(v.x), "r"(v.y), "r"(v.z), "r"(v.w));
        }
    }
    __syncthreads();
    uint32_t qf[4][4];
    {
        uint32_t qrow = (uint32_t)(w*16 + (lane & 15));
        uint32_t qc = (uint32_t)((lane >> 4) << 4);
        #pragma unroll
        for (int kt = 0; kt < 4; ++kt) {
            uint32_t c = ((uint32_t)(kt*32) + qc) ^ x;
            ldm_x4(qf[kt], sbse + ASTG + qrow * 128 + c);
        }
    }
    __syncthreads();            // all warps have Q frags; stage 1 reusable

    float oc[8][4] = {};
    float m0r = NEG_INF, m1r = NEG_INF, l0r = 0.f, l1r = 0.f;
    uint32_t krow = (uint32_t)(lane & 7);
    uint32_t kq16 = (uint32_t)((lane >> 3) << 4);
    uint32_t vlr = (uint32_t)(lane & 15);
    uint32_t vsel = (uint32_t)((lane >> 4) << 4);
    const float SC2 = 0.125f * LOG2E;

    const int NT = SEQ / 64;   // 32
    for (int it = 0; it < NT; ++it) {
        CP_WAIT(0);
        __syncthreads();     // stage it visible; all warps done with it-1
        if (it + 1 < NT) { issueKV(it + 1); CP_COMMIT(); }

        uint32_t stage = sbse + (uint32_t)(it & 1) * ASTG;
        const uint32_t KhB = stage;
        const uint32_t VhB = stage + 8192;
        const float* km = kmf + (it & 1) * 64;

        // S = Qh Kh^T  (16 rows x 64 keys per warp)
        float sc[8][4] = {};
        #pragma unroll
        for (int nt = 0; nt < 8; ++nt) {
            uint32_t rbase = ((uint32_t)(nt*8) + krow) * 128;
            #pragma unroll
            for (int ktp = 0; ktp < 2; ++ktp) {
                uint32_t c = ((uint32_t)(ktp*64) + kq16) ^ x;
                uint32_t kh4[4];
                ldm_x4(kh4, KhB + rbase + c);
                mma16816(sc[nt], qf[2*ktp],   kh4);
                mma16816(sc[nt], qf[2*ktp+1], kh4 + 2);
            }
        }

        // online softmax in exp2 domain
        float r0m = NEG_INF, r1m = NEG_INF;
        #pragma unroll
        for (int nt = 0; nt < 8; ++nt) {
            float a0 = km[nt*8 + cq], a1 = km[nt*8 + cq + 1];
            sc[nt][0] = sc[nt][0]*SC2 + a0;
            sc[nt][1] = sc[nt][1]*SC2 + a1;
            sc[nt][2] = sc[nt][2]*SC2 + a0;
            sc[nt][3] = sc[nt][3]*SC2 + a1;
            r0m = fmaxf(r0m, fmaxf(sc[nt][0], sc[nt][1]));
            r1m = fmaxf(r1m, fmaxf(sc[nt][2], sc[nt][3]));
        }
        r0m = fmaxf(r0m, __shfl_xor_sync(0xffffffffu, r0m, 1));
        r0m = fmaxf(r0m, __shfl_xor_sync(0xffffffffu, r0m, 2));
        r1m = fmaxf(r1m, __shfl_xor_sync(0xffffffffu, r1m, 1));
        r1m = fmaxf(r1m, __shfl_xor_sync(0xffffffffu, r1m, 2));
        float mn0 = fmaxf(m0r, r0m), mn1 = fmaxf(m1r, r1m);
        float ms0 = (mn0 == NEG_INF) ? 0.0f : mn0;
        float ms1 = (mn1 == NEG_INF) ? 0.0f : mn1;
        float al0 = exp2f(m0r - ms0), al1 = exp2f(m1r - ms1);
        m0r = mn0; m1r = mn1;

        // exp2 + pack P (fp16 hi) directly into PV A-fragment registers
        uint32_t ph[8], ph2[8];
        float rs0 = 0.f, rs1 = 0.f;
        #pragma unroll
        for (int nt = 0; nt < 8; ++nt) {
            float p0 = exp2f(sc[nt][0] - ms0), p1 = exp2f(sc[nt][1] - ms0);
            float p2 = exp2f(sc[nt][2] - ms1), p3 = exp2f(sc[nt][3] - ms1);
            rs0 += p0 + p1; rs1 += p2 + p3;
            __half2 hv0 = __floats2half2_rn(p0, p1);
            __half2 hv1 = __floats2half2_rn(p2, p3);
            ph[nt]  = *(uint32_t*)&hv0;
            ph2[nt] = *(uint32_t*)&hv1;
        }
        rs0 += __shfl_xor_sync(0xffffffffu, rs0, 1);
        rs0 += __shfl_xor_sync(0xffffffffu, rs0, 2);
        rs1 += __shfl_xor_sync(0xffffffffu, rs1, 1);
        rs1 += __shfl_xor_sync(0xffffffffu, rs1, 2);
        l0r = l0r * al0 + rs0;
        l1r = l1r * al1 + rs1;
        #pragma unroll
        for (int nt = 0; nt < 8; ++nt) {
            oc[nt][0] *= al0; oc[nt][1] *= al0;
            oc[nt][2] *= al1; oc[nt][3] *= al1;
        }

        // O += Ph Vh
        #pragma unroll
        for (int kt = 0; kt < 4; ++kt) {
            uint32_t pa[4] = {ph[2*kt], ph2[2*kt], ph[2*kt+1], ph2[2*kt+1]};
            uint32_t vr = ((uint32_t)(kt*16) + vlr) * 128;
            #pragma unroll
            for (int ntp = 0; ntp < 4; ++ntp) {
                uint32_t c = ((uint32_t)(ntp*32) + vsel) ^ x;
                uint32_t vh4[4];
                ldm_x4t(vh4, VhB + vr + c);
                mma16816(oc[2*ntp],   pa, vh4);
                mma16816(oc[2*ntp+1], pa, vh4 + 2);
            }
        }
    }

    // epilogue: normalize, zero masked query rows, write (b,s,d) as fp16 hi
    int r0 = w*16 + g, r1 = r0 + 8;
    float inv0 = (mb[q0 + r0] && l0r > 0.f) ? 1.0f / l0r : 0.0f;
    float inv1 = (mb[q0 + r1] && l1r > 0.f) ? 1.0f / l1r : 0.0f;
    size_t base0 = ((size_t)b*SEQ + q0 + r0)*DMODEL + h*HDIM;
    size_t base1 = ((size_t)b*SEQ + q0 + r1)*DMODEL + h*HDIM;
    #pragma unroll
    for (int nt = 0; nt < 8; ++nt) {
        __half2 h0 = __floats2half2_rn(oc[nt][0]*inv0, oc[nt][1]*inv0);
        __half2 h1 = __floats2half2_rn(oc[nt][2]*inv1, oc[nt][3]*inv1);
        *(__half2*)(obh + base0 + nt*8 + cq) = h0;
        *(__half2*)(obh + base1 + nt*8 + cq) = h1;
    }
}

// ---------------- launch ----------------------------------------------------
extern "C" void kernel_launch(void* const* d_in, const int* in_sizes, int n_in,
                              void* d_out, int out_size) {
    const float* q    = (const float*)d_in[0];
    const unsigned char* mask = (const unsigned char*)d_in[1];
    const float* Wq   = (const float*)d_in[2];
    const float* bq   = (const float*)d_in[3];
    const float* Wk   = (const float*)d_in[4];
    const float* bk   = (const float*)d_in[5];
    const float* Wv   = (const float*)d_in[6];
    const float* bv   = (const float*)d_in[7];
    const float* Wo   = (const float*)d_in[8];
    const float* bo   = (const float*)d_in[9];
    float* out = (float*)d_out;

    __half *ah, *wh, *wl, *qhh, *khh, *vhh, *oh;
    cudaGetSymbolAddress((void**)&ah,  g_ah);
    cudaGetSymbolAddress((void**)&wh,  g_wh);
    cudaGetSymbolAddress((void**)&wl,  g_wl);
    cudaGetSymbolAddress((void**)&qhh, g_qhh);
    cudaGetSymbolAddress((void**)&khh, g_khh);
    cudaGetSymbolAddress((void**)&vhh, g_vhh);
    cudaGetSymbolAddress((void**)&oh,  g_oh);

    detect_mask_kernel<<<1, 256>>>(mask);
    convert_mask_kernel<<<(BATCH*SEQ + 255) / 256, 256>>>(mask);

    tohalf_kernel<<<NELEM / 1024, 256>>>(q, ah, NELEM);
    split_w_kernel<<<dim3(1024, 1, 4), 256>>>(Wq, Wk, Wv, Wo, wh, wl);

    const int qkv_smem = 2 * 32768;   // 65536 B
    const int opj_smem = 2 * 49152;   // 98304 B
    static bool attr_done = false;
    if (!attr_done) {
        cudaFuncSetAttribute((const void*)gemm_cp_kernel<true, false>,
                             cudaFuncAttributeMaxDynamicSharedMemorySize, qkv_smem);
        cudaFuncSetAttribute((const void*)gemm_cp_kernel<false, true>,
                             cudaFuncAttributeMaxDynamicSharedMemorySize, opj_smem);
        cudaFuncSetAttribute((const void*)attn_cp_kernel,
                             cudaFuncAttributeMaxDynamicSharedMemorySize, ATTN_SMEM);
        attr_done = true;
    }

    // fused QKV projections (W hi only; outputs fp16 hi)
    gemm_cp_kernel<true, false><<<dim3(8, 64, 3), 256, qkv_smem>>>(
        ah, wh, wl, 0, bq, bk, bv,
        qhh, khh, vhh, nullptr);

    attn_cp_kernel<<<dim3(SEQ / 128, BATCH * NHEAD), 256, ATTN_SMEM>>>(
        qhh, khh, vhh, oh);

    // output projection (W hi+lo) -> fp32 out
    gemm_cp_kernel<false, true><<<dim3(8, 64, 1), 256, opj_smem>>>(
        oh, wh, wl, 3, bo, bo, bo,
        nullptr, nullptr, nullptr, out);
}